// round 2
// baseline (speedup 1.0000x reference)
#include <cuda_runtime.h>
#include <math.h>

#define NB 2
#define NL 2048
#define NK 48
#define NH 128
#define IN3 384
#define BL (NB*NL)
#define SCALE_INV (1.0f/30.0f)
#define LNEPS 1e-5f

__device__ float g_hV1[(long)BL*NH];

__device__ __forceinline__ float gelu_f(float x) {
    return 0.5f * x * (1.0f + erff(x * 0.70710678118654752f));
}

__device__ __forceinline__ float warp_sum(float v) {
    #pragma unroll
    for (int o = 16; o > 0; o >>= 1) v += __shfl_xor_sync(0xffffffffu, v, o);
    return v;
}

// 48xKdim X (in smem, row stride ldx) times Kdim x 128 weight (global, staged
// through Ws[32][128] smem chunks). Each thread computes a 6-row x 4-col tile.
__device__ __forceinline__ void gemm48(const float* __restrict__ Xin, int ldx, int Kdim,
                                       const float* __restrict__ Wg, float* Ws,
                                       int cg, int rg, int tid, float acc[6][4])
{
    #pragma unroll
    for (int i = 0; i < 6; i++) { acc[i][0]=0.f; acc[i][1]=0.f; acc[i][2]=0.f; acc[i][3]=0.f; }
    for (int kk = 0; kk < Kdim; kk += 32) {
        for (int u = tid; u < 32*32; u += 256) {
            int wr = u >> 5, wc = u & 31;
            ((float4*)(Ws + wr*NH))[wc] = ((const float4*)(Wg + (long)(kk+wr)*NH))[wc];
        }
        __syncthreads();
        #pragma unroll
        for (int k = 0; k < 32; k++) {
            float4 w = ((const float4*)(Ws + k*NH))[cg];
            #pragma unroll
            for (int i = 0; i < 6; i++) {
                float x = Xin[(rg*6+i)*ldx + kk + k];
                acc[i][0] += x*w.x; acc[i][1] += x*w.y;
                acc[i][2] += x*w.z; acc[i][3] += x*w.w;
            }
        }
        __syncthreads();
    }
}

// EDGE=false: node message stage -> masked K-reduction, residual+LN, write h_V1
// EDGE=true : edge update stage  -> per-edge residual+LN, write h_E_out
template<bool EDGE>
__global__ __launch_bounds__(256, 1)
void mlp_kernel(const float* __restrict__ hVin,
                const float* __restrict__ hE,
                const int* __restrict__ Eidx,
                const float* __restrict__ maskA,
                const float* __restrict__ W_1, const float* __restrict__ B_1,
                const float* __restrict__ W_2, const float* __restrict__ B_2,
                const float* __restrict__ W_3, const float* __restrict__ B_3,
                const float* __restrict__ lns, const float* __restrict__ lnb,
                float* __restrict__ out)
{
    extern __shared__ float sm[];
    float* Xs = sm;                       // [48][384]
    float* Ws = Xs + NK*IN3;              // [32][128]
    float* M1 = Ws + 32*NH;               // [48][128]
    float* M2 = M1 + NK*NH;               // [48][128]
    __shared__ int   idxs[NK];
    __shared__ float maskr[NK];
    __shared__ float red[16];

    const int tid = threadIdx.x;
    const int bid = blockIdx.x;
    const int b   = bid >> 11;            // L = 2048
    const long baselk = (long)bid * NK;

    if (tid < NK) {
        idxs[tid]  = Eidx[baselk + tid];
        maskr[tid] = maskA[baselk + tid];
    }
    __syncthreads();

    const float* hv_c = hVin + (long)bid * NH;

    // Build X = [h_V(center) | h_E row | h_V(gathered)]  (48 x 384)
    for (int t = tid; t < NK*96; t += 256) {
        int r = t / 96;
        int s = t - r*96;
        float4 v;
        if (s < 32)      v = ((const float4*)hv_c)[s];
        else if (s < 64) v = ((const float4*)(hE + (baselk + r)*NH))[s-32];
        else             v = ((const float4*)(hVin + ((long)b*NL + idxs[r])*NH))[s-64];
        ((float4*)(Xs + r*IN3))[s] = v;
    }
    __syncthreads();

    const int cg = tid & 31;
    const int rg = tid >> 5;
    float acc[6][4];

    // layer 1
    gemm48(Xs, IN3, IN3, W_1, Ws, cg, rg, tid, acc);
    {
        float4 bv = ((const float4*)B_1)[cg];
        #pragma unroll
        for (int i = 0; i < 6; i++) {
            float4 o;
            o.x = gelu_f(acc[i][0]+bv.x); o.y = gelu_f(acc[i][1]+bv.y);
            o.z = gelu_f(acc[i][2]+bv.z); o.w = gelu_f(acc[i][3]+bv.w);
            ((float4*)(M1 + (rg*6+i)*NH))[cg] = o;
        }
    }
    __syncthreads();

    // layer 2
    gemm48(M1, NH, NH, W_2, Ws, cg, rg, tid, acc);
    {
        float4 bv = ((const float4*)B_2)[cg];
        #pragma unroll
        for (int i = 0; i < 6; i++) {
            float4 o;
            o.x = gelu_f(acc[i][0]+bv.x); o.y = gelu_f(acc[i][1]+bv.y);
            o.z = gelu_f(acc[i][2]+bv.z); o.w = gelu_f(acc[i][3]+bv.w);
            ((float4*)(M2 + (rg*6+i)*NH))[cg] = o;
        }
    }
    __syncthreads();

    // layer 3
    gemm48(M2, NH, NH, W_3, Ws, cg, rg, tid, acc);

    if (!EDGE) {
        float4 bv = ((const float4*)B_3)[cg];
        #pragma unroll
        for (int i = 0; i < 6; i++) {
            int r = rg*6 + i;
            float mk = maskr[r];
            float4 o;
            o.x = (acc[i][0]+bv.x)*mk; o.y = (acc[i][1]+bv.y)*mk;
            o.z = (acc[i][2]+bv.z)*mk; o.w = (acc[i][3]+bv.w)*mk;
            ((float4*)(M1 + r*NH))[cg] = o;
        }
        __syncthreads();
        // reduce over K, residual, LayerNorm
        if (tid < NH) {
            float s = 0.f;
            #pragma unroll 8
            for (int r = 0; r < NK; r++) s += M1[r*NH + tid];
            Ws[tid] = hv_c[tid] + s * SCALE_INV;
        }
        __syncthreads();
        if (tid < NH) {
            float s = warp_sum(Ws[tid]);
            if ((tid & 31) == 0) red[tid>>5] = s;
        }
        __syncthreads();
        float mu = (red[0]+red[1]+red[2]+red[3]) * (1.0f/NH);
        if (tid < NH) {
            float d = Ws[tid] - mu;
            float q = warp_sum(d*d);
            if ((tid & 31) == 0) red[4 + (tid>>5)] = q;
        }
        __syncthreads();
        if (tid < NH) {
            float var = (red[4]+red[5]+red[6]+red[7]) * (1.0f/NH);
            float d = Ws[tid] - mu;
            out[(long)bid*NH + tid] = d * rsqrtf(var + LNEPS) * lns[tid] + lnb[tid];
        }
    } else {
        float4 bv = ((const float4*)B_3)[cg];
        #pragma unroll
        for (int i = 0; i < 6; i++) {
            int r = rg*6 + i;
            float4 o;
            o.x = acc[i][0]+bv.x; o.y = acc[i][1]+bv.y;
            o.z = acc[i][2]+bv.z; o.w = acc[i][3]+bv.w;
            ((float4*)(M1 + r*NH))[cg] = o;
        }
        __syncthreads();
        int wid = tid >> 5, lane = tid & 31;
        float4 sV = ((const float4*)lns)[lane];
        float4 bV = ((const float4*)lnb)[lane];
        #pragma unroll
        for (int rr = 0; rr < 6; rr++) {
            int r = wid*6 + rr;
            float4 e = ((const float4*)(hE + (baselk + r)*NH))[lane];
            float4 m = ((const float4*)(M1 + r*NH))[lane];
            float4 v;
            v.x = e.x+m.x; v.y = e.y+m.y; v.z = e.z+m.z; v.w = e.w+m.w;
            float mu = warp_sum(v.x+v.y+v.z+v.w) * (1.0f/NH);
            float dx=v.x-mu, dy=v.y-mu, dz=v.z-mu, dw=v.w-mu;
            float var = warp_sum(dx*dx+dy*dy+dz*dz+dw*dw) * (1.0f/NH);
            float inv = rsqrtf(var + LNEPS);
            float4 o;
            o.x = dx*inv*sV.x + bV.x; o.y = dy*inv*sV.y + bV.y;
            o.z = dz*inv*sV.z + bV.z; o.w = dw*inv*sV.w + bV.w;
            ((float4*)(out + (baselk + r)*NH))[lane] = o;
        }
    }
}

// Position-wise FFN: 16 rows per CTA, fused gelu/residual/LN/mask
__global__ __launch_bounds__(256, 1)
void ffn_kernel(const float* __restrict__ hV1,
                const float* __restrict__ maskV,
                const float* __restrict__ Wi, const float* __restrict__ bi,
                const float* __restrict__ Wo, const float* __restrict__ bo,
                const float* __restrict__ lns, const float* __restrict__ lnb,
                float* __restrict__ out)
{
    extern __shared__ float sm[];
    float* Xr = sm;            // [16][128]
    float* Hd = Xr + 16*NH;    // [16][512]
    float* Wc = Hd + 16*512;   // [16][512] (layer1) / [32][128] (layer2)

    const int tid = threadIdx.x;
    const long row0 = (long)blockIdx.x * 16;

    for (int t = tid; t < 16*32; t += 256) {
        int r = t >> 5, c = t & 31;
        ((float4*)(Xr + r*NH))[c] = ((const float4*)(hV1 + (row0+r)*NH))[c];
    }
    __syncthreads();

    // layer 1: [16][128] @ Wi[128][512], gelu
    {
        int cg = tid & 63;   // cols cg*8..+7
        int rg = tid >> 6;   // rows rg*4..+3
        float acc[4][8];
        #pragma unroll
        for (int i = 0; i < 4; i++)
            #pragma unroll
            for (int j = 0; j < 8; j++) acc[i][j] = 0.f;
        for (int kk = 0; kk < NH; kk += 16) {
            for (int u = tid; u < 16*128; u += 256) {
                int wr = u >> 7, wc = u & 127;
                ((float4*)(Wc + wr*512))[wc] = ((const float4*)(Wi + (long)(kk+wr)*512))[wc];
            }
            __syncthreads();
            #pragma unroll
            for (int k = 0; k < 16; k++) {
                float4 w0 = ((const float4*)(Wc + k*512))[cg*2];
                float4 w1 = ((const float4*)(Wc + k*512))[cg*2+1];
                #pragma unroll
                for (int i = 0; i < 4; i++) {
                    float x = Xr[(rg*4+i)*NH + kk + k];
                    acc[i][0]+=x*w0.x; acc[i][1]+=x*w0.y; acc[i][2]+=x*w0.z; acc[i][3]+=x*w0.w;
                    acc[i][4]+=x*w1.x; acc[i][5]+=x*w1.y; acc[i][6]+=x*w1.z; acc[i][7]+=x*w1.w;
                }
            }
            __syncthreads();
        }
        float4 b0 = ((const float4*)bi)[cg*2];
        float4 b1 = ((const float4*)bi)[cg*2+1];
        #pragma unroll
        for (int i = 0; i < 4; i++) {
            int r = rg*4 + i;
            float4 o0, o1;
            o0.x = gelu_f(acc[i][0]+b0.x); o0.y = gelu_f(acc[i][1]+b0.y);
            o0.z = gelu_f(acc[i][2]+b0.z); o0.w = gelu_f(acc[i][3]+b0.w);
            o1.x = gelu_f(acc[i][4]+b1.x); o1.y = gelu_f(acc[i][5]+b1.y);
            o1.z = gelu_f(acc[i][6]+b1.z); o1.w = gelu_f(acc[i][7]+b1.w);
            ((float4*)(Hd + r*512))[cg*2]   = o0;
            ((float4*)(Hd + r*512))[cg*2+1] = o1;
        }
    }
    __syncthreads();

    // layer 2: Hd[16][512] @ Wo[512][128], + bias + residual
    {
        int cg = tid & 63;   // cols cg*2, cg*2+1
        int rg = tid >> 6;
        float acc[4][2];
        #pragma unroll
        for (int i = 0; i < 4; i++) { acc[i][0]=0.f; acc[i][1]=0.f; }
        for (int kk = 0; kk < 512; kk += 32) {
            for (int u = tid; u < 32*32; u += 256) {
                int wr = u >> 5, wc = u & 31;
                ((float4*)(Wc + wr*NH))[wc] = ((const float4*)(Wo + (long)(kk+wr)*NH))[wc];
            }
            __syncthreads();
            #pragma unroll
            for (int k = 0; k < 32; k++) {
                float2 w = ((const float2*)(Wc + k*NH))[cg];
                #pragma unroll
                for (int i = 0; i < 4; i++) {
                    float x = Hd[(rg*4+i)*512 + kk + k];
                    acc[i][0] += x*w.x; acc[i][1] += x*w.y;
                }
            }
            __syncthreads();
        }
        float2 bv = ((const float2*)bo)[cg];
        #pragma unroll
        for (int i = 0; i < 4; i++) {
            int r = rg*4 + i;
            float2 z;
            z.x = acc[i][0] + bv.x + Xr[r*NH + cg*2];
            z.y = acc[i][1] + bv.y + Xr[r*NH + cg*2 + 1];
            ((float2*)(Hd + r*NH))[cg] = z;   // reuse Hd front as Out[16][128]
        }
    }
    __syncthreads();

    // per-row LN + mask_V
    {
        int wid = tid >> 5, lane = tid & 31;
        float4 sV = ((const float4*)lns)[lane];
        float4 bV = ((const float4*)lnb)[lane];
        #pragma unroll
        for (int rr = 0; rr < 2; rr++) {
            int r = wid*2 + rr;
            long grow = row0 + r;
            float mk = maskV[grow];
            float4 v = ((const float4*)(Hd + r*NH))[lane];
            float mu = warp_sum(v.x+v.y+v.z+v.w) * (1.0f/NH);
            float dx=v.x-mu, dy=v.y-mu, dz=v.z-mu, dw=v.w-mu;
            float var = warp_sum(dx*dx+dy*dy+dz*dz+dw*dw) * (1.0f/NH);
            float inv = rsqrtf(var + LNEPS);
            float4 o;
            o.x = (dx*inv*sV.x + bV.x)*mk; o.y = (dy*inv*sV.y + bV.y)*mk;
            o.z = (dz*inv*sV.z + bV.z)*mk; o.w = (dw*inv*sV.w + bV.w)*mk;
            ((float4*)(out + grow*NH))[lane] = o;
        }
    }
}

extern "C" void kernel_launch(void* const* d_in, const int* in_sizes, int n_in,
                              void* d_out, int out_size) {
    (void)in_sizes; (void)n_in; (void)out_size;
    const float* hV    = (const float*)d_in[0];
    const float* hE    = (const float*)d_in[1];
    const int*   Eidx  = (const int*)d_in[2];     // JAX default x64-disabled -> int32
    const float* maskV = (const float*)d_in[3];
    const float* maskA = (const float*)d_in[4];
    const float *W1 =(const float*)d_in[5],  *b1 =(const float*)d_in[6];
    const float *W2 =(const float*)d_in[7],  *b2 =(const float*)d_in[8];
    const float *W3 =(const float*)d_in[9],  *b3 =(const float*)d_in[10];
    const float *W11=(const float*)d_in[11], *b11=(const float*)d_in[12];
    const float *W12=(const float*)d_in[13], *b12=(const float*)d_in[14];
    const float *W13=(const float*)d_in[15], *b13=(const float*)d_in[16];
    const float *Wi =(const float*)d_in[17], *bi =(const float*)d_in[18];
    const float *Wo =(const float*)d_in[19], *bo =(const float*)d_in[20];
    const float *ln1s=(const float*)d_in[21], *ln1b=(const float*)d_in[22];
    const float *ln2s=(const float*)d_in[23], *ln2b=(const float*)d_in[24];
    const float *ln3s=(const float*)d_in[25], *ln3b=(const float*)d_in[26];

    float* outV = (float*)d_out;
    float* outE = outV + (long)BL*NH;

    float* hV1 = nullptr;
    cudaGetSymbolAddress((void**)&hV1, g_hV1);

    const int sm1 = (NK*IN3 + 32*NH + 2*NK*NH) * (int)sizeof(float);   // 139264
    const int sm2 = (16*NH + 16*512 + 16*512) * (int)sizeof(float);    // 73728
    cudaFuncSetAttribute(mlp_kernel<false>, cudaFuncAttributeMaxDynamicSharedMemorySize, sm1);
    cudaFuncSetAttribute(mlp_kernel<true>,  cudaFuncAttributeMaxDynamicSharedMemorySize, sm1);
    cudaFuncSetAttribute(ffn_kernel,        cudaFuncAttributeMaxDynamicSharedMemorySize, sm2);

    mlp_kernel<false><<<BL, 256, sm1>>>(hV, hE, Eidx, maskA,
                                        W1, b1, W2, b2, W3, b3, ln1s, ln1b, hV1);
    ffn_kernel<<<BL/16, 256, sm2>>>(hV1, maskV, Wi, bi, Wo, bo, ln2s, ln2b, outV);
    mlp_kernel<true><<<BL, 256, sm1>>>(outV, hE, Eidx, maskA,
                                       W11, b11, W12, b12, W13, b13, ln3s, ln3b, outE);
}

// round 4
// speedup vs baseline: 2.0265x; 2.0265x over previous
#include <cuda_runtime.h>
#include <cuda_bf16.h>
#include <math.h>
#include <stdint.h>

#define NB 2
#define NL 2048
#define NK 48
#define NH 128
#define BL (NB*NL)              // 4096
#define NEDGE (BL*NK)           // 196608
#define NTILE (NEDGE/128)       // 1536
#define SCALE_INV (1.0f/30.0f)
#define LNEPS 1e-5f

// padded smem row stride (bf16 elements): 136*2 = 272B -> conflict-free ldmatrix
#define LDS_STRIDE 136
// byte offsets inside the 1024-aligned dynamic smem block
#define A_HI 0
#define A_LO 34816            // 128*136*2
#define B_HI 69632
#define B_LO 104448
#define SM_BYTES 139264
#define DSMEM_TOTAL (SM_BYTES + 1024)
// fp32 stage buffer (aliases B_HI..): padded stride 132 floats
#define STG_STRIDE 132

// ---- transposed + hi/lo split weights (K-major [N=128][Ktot]) ----
__device__ __align__(16) __nv_bfloat16 g_W1h[128*384],  g_W1l[128*384];
__device__ __align__(16) __nv_bfloat16 g_W2h[128*128],  g_W2l[128*128];
__device__ __align__(16) __nv_bfloat16 g_W3h[128*128],  g_W3l[128*128];
__device__ __align__(16) __nv_bfloat16 g_W11h[128*384], g_W11l[128*384];
__device__ __align__(16) __nv_bfloat16 g_W12h[128*128], g_W12l[128*128];
__device__ __align__(16) __nv_bfloat16 g_W13h[128*128], g_W13l[128*128];
__device__ float g_psum[2L*BL*NH];       // 2 slots per node
__device__ float g_hV1[(long)BL*NH];

// ============================ helpers ============================
__device__ __forceinline__ uint32_t smem_u32(const void* p) {
    uint32_t a;
    asm("{ .reg .u64 t; cvta.to.shared.u64 t, %1; cvt.u32.u64 %0, t; }" : "=r"(a) : "l"(p));
    return a;
}
__device__ __forceinline__ void ldsm_x4(uint32_t* r, uint32_t addr) {
    asm volatile("ldmatrix.sync.aligned.m8n8.x4.shared.b16 {%0,%1,%2,%3}, [%4];"
        : "=r"(r[0]), "=r"(r[1]), "=r"(r[2]), "=r"(r[3]) : "r"(addr));
}
__device__ __forceinline__ void ldsm_x2(uint32_t* r, uint32_t addr) {
    asm volatile("ldmatrix.sync.aligned.m8n8.x2.shared.b16 {%0,%1}, [%2];"
        : "=r"(r[0]), "=r"(r[1]) : "r"(addr));
}
__device__ __forceinline__ void mma16816(float* d, const uint32_t* a, const uint32_t* b) {
    asm volatile("mma.sync.aligned.m16n8k16.row.col.f32.bf16.bf16.f32 "
        "{%0,%1,%2,%3}, {%4,%5,%6,%7}, {%8,%9}, {%0,%1,%2,%3};"
        : "+f"(d[0]), "+f"(d[1]), "+f"(d[2]), "+f"(d[3])
        : "r"(a[0]), "r"(a[1]), "r"(a[2]), "r"(a[3]), "r"(b[0]), "r"(b[1]));
}
__device__ __forceinline__ float gelu_f(float x) {
    return 0.5f * x * (1.0f + erff(x * 0.70710678118654752f));
}
__device__ __forceinline__ float warp_sum(float v) {
    #pragma unroll
    for (int o = 16; o > 0; o >>= 1) v += __shfl_xor_sync(0xffffffffu, v, o);
    return v;
}
// split x,y to packed hi-bf16x2 and lo-bf16x2
__device__ __forceinline__ void split2(float x, float y, uint32_t& hp, uint32_t& lp) {
    __nv_bfloat16 hx = __float2bfloat16(x), hy = __float2bfloat16(y);
    float lx = x - __bfloat162float(hx), ly = y - __bfloat162float(hy);
    hp = ((uint32_t)__bfloat16_as_ushort(hy) << 16) | __bfloat16_as_ushort(hx);
    __nv_bfloat16 lbx = __float2bfloat16(lx), lby = __float2bfloat16(ly);
    lp = ((uint32_t)__bfloat16_as_ushort(lby) << 16) | __bfloat16_as_ushort(lbx);
}

// ============================ prep: transpose + split weights ============================
__device__ __forceinline__ void split_tr(const float* __restrict__ W, __nv_bfloat16* H,
                                         __nv_bfloat16* L, int K, int g, int gs) {
    for (int i = g; i < K * 128; i += gs) {
        int n = i & 127, k = i >> 7;
        float v = W[(long)k * 128 + n];
        __nv_bfloat16 h = __float2bfloat16(v);
        float lo = v - __bfloat162float(h);
        H[(long)n * K + k] = h;
        L[(long)n * K + k] = __float2bfloat16(lo);
    }
}
__global__ void prep_weights(const float* W1, const float* W2, const float* W3,
                             const float* W11, const float* W12, const float* W13) {
    int g = blockIdx.x * blockDim.x + threadIdx.x;
    int gs = gridDim.x * blockDim.x;
    split_tr(W1,  g_W1h,  g_W1l,  384, g, gs);
    split_tr(W2,  g_W2h,  g_W2l,  128, g, gs);
    split_tr(W3,  g_W3h,  g_W3l,  128, g, gs);
    split_tr(W11, g_W11h, g_W11l, 384, g, gs);
    split_tr(W12, g_W12h, g_W12l, 128, g, gs);
    split_tr(W13, g_W13h, g_W13l, 128, g, gs);
}

// ============================ MMA stage ============================
__device__ __forceinline__ void loadB_tile(const __nv_bfloat16* __restrict__ Wh,
                                           const __nv_bfloat16* __restrict__ Wl,
                                           int Ktot, int kk, char* smA, int tid) {
    __nv_bfloat16* Bh = (__nv_bfloat16*)(smA + B_HI);
    __nv_bfloat16* Bl = (__nv_bfloat16*)(smA + B_LO);
    for (int u = tid; u < 128 * 32; u += 256) {
        int n = u >> 5, q = u & 31;                       // q: 4-bf16 group
        uint2 vh = *(const uint2*)(Wh + (long)n * Ktot + kk + q * 4);
        uint2 vl = *(const uint2*)(Wl + (long)n * Ktot + kk + q * 4);
        *(uint2*)(Bh + n * LDS_STRIDE + q * 4) = vh;
        *(uint2*)(Bl + n * LDS_STRIDE + q * 4) = vl;
    }
}

// one 128-K chunk of MMA: 8 k-steps, 3-combo hi/lo split
__device__ __forceinline__ void gemm_chunk(char* smA, int lane, int mbase, int nbase,
                                           float acc[2][8][4]) {
    const uint32_t sb = smem_u32(smA);
    // A ldmatrix lane address (x4): row = mbase + (lane&15), col = (lane>>4)*8
    const uint32_t aOff = (uint32_t)(((mbase + (lane & 15)) * LDS_STRIDE + ((lane >> 4) << 3)) * 2);
    // B ldmatrix lane address (x2): l = lane&15: row n = nbase + (l&7), col = (l>>3)*8
    const int l = lane & 15;
    const uint32_t bOff = (uint32_t)((((nbase + (l & 7)) * LDS_STRIDE) + ((l >> 3) << 3)) * 2);

    #pragma unroll
    for (int ks = 0; ks < 8; ks++) {
        const uint32_t k0b = ks * 32;   // 16 bf16 = 32 bytes
        uint32_t ah[2][4], al[2][4];
        ldsm_x4(ah[0], sb + A_HI + aOff + k0b);
        ldsm_x4(ah[1], sb + A_HI + aOff + k0b + 16 * LDS_STRIDE * 2);
        ldsm_x4(al[0], sb + A_LO + aOff + k0b);
        ldsm_x4(al[1], sb + A_LO + aOff + k0b + 16 * LDS_STRIDE * 2);
        uint32_t bh[8][2], bl[8][2];
        #pragma unroll
        for (int nt = 0; nt < 8; nt++) {
            uint32_t ba = bOff + nt * (8 * LDS_STRIDE * 2) + k0b;
            ldsm_x2(bh[nt], sb + B_HI + ba);
            ldsm_x2(bl[nt], sb + B_LO + ba);
        }
        #pragma unroll
        for (int mt = 0; mt < 2; mt++)
            #pragma unroll
            for (int nt = 0; nt < 8; nt++) {
                mma16816(acc[mt][nt], ah[mt], bh[nt]);
                mma16816(acc[mt][nt], ah[mt], bl[nt]);
                mma16816(acc[mt][nt], al[mt], bh[nt]);
            }
    }
}

__device__ __forceinline__ void zero_acc(float acc[2][8][4]) {
    #pragma unroll
    for (int mt = 0; mt < 2; mt++)
        #pragma unroll
        for (int nt = 0; nt < 8; nt++)
            #pragma unroll
            for (int j = 0; j < 4; j++) acc[mt][nt][j] = 0.f;
}

// bias + gelu + hi/lo split back into A smem
__device__ __forceinline__ void epi_gelu_to_A(float acc[2][8][4], const float* __restrict__ bias,
                                              char* smA, int lane, int mbase, int nbase) {
    __nv_bfloat16* Ah = (__nv_bfloat16*)(smA + A_HI);
    __nv_bfloat16* Al = (__nv_bfloat16*)(smA + A_LO);
    int g = lane >> 2, tig = lane & 3;
    #pragma unroll
    for (int mt = 0; mt < 2; mt++) {
        #pragma unroll
        for (int nt = 0; nt < 8; nt++) {
            int col = nbase + nt * 8 + tig * 2;
            float2 b2 = *(const float2*)(bias + col);
            float x0 = gelu_f(acc[mt][nt][0] + b2.x);
            float x1 = gelu_f(acc[mt][nt][1] + b2.y);
            float x2 = gelu_f(acc[mt][nt][2] + b2.x);
            float x3 = gelu_f(acc[mt][nt][3] + b2.y);
            int row0 = mbase + mt * 16 + g;
            uint32_t hp, lp;
            split2(x0, x1, hp, lp);
            *(uint32_t*)(Ah + row0 * LDS_STRIDE + col) = hp;
            *(uint32_t*)(Al + row0 * LDS_STRIDE + col) = lp;
            split2(x2, x3, hp, lp);
            *(uint32_t*)(Ah + (row0 + 8) * LDS_STRIDE + col) = hp;
            *(uint32_t*)(Al + (row0 + 8) * LDS_STRIDE + col) = lp;
        }
    }
}

template<bool EDGE>
__global__ __launch_bounds__(256, 1)
void mma_stage(const float* __restrict__ hVin,
               const float* __restrict__ hE,
               const int* __restrict__ Eidx,
               const float* __restrict__ maskA,
               const float* __restrict__ B1v, const float* __restrict__ B2v,
               const float* __restrict__ B3v,
               const float* __restrict__ lns, const float* __restrict__ lnb,
               float* __restrict__ outp) {
    extern __shared__ char dsm[];
    char* smA = (char*)(((uintptr_t)dsm + 1023) & ~(uintptr_t)1023);
    float* stage = (float*)(smA + B_HI);          // aliases B after last MMA

    __shared__ int   gcent[128];
    __shared__ int   gnb[128];
    __shared__ float mkr[128];

    const int tid = threadIdx.x, wid = tid >> 5, lane = tid & 31;
    const long base = (long)blockIdx.x * 128;
    const int mbase = (wid & 3) * 32;
    const int nbase = (wid >> 2) * 64;

    if (tid < 128) {
        long e = base + tid;
        int n = (int)(e / NK);
        gcent[tid] = n;
        gnb[tid] = (n >> 11) * NL + Eidx[e];
        if (!EDGE) mkr[tid] = maskA[e]; else mkr[tid] = 1.f;
    }

    const __nv_bfloat16* W1h = EDGE ? g_W11h : g_W1h;
    const __nv_bfloat16* W1l = EDGE ? g_W11l : g_W1l;
    const __nv_bfloat16* W2h = EDGE ? g_W12h : g_W2h;
    const __nv_bfloat16* W2l = EDGE ? g_W12l : g_W2l;
    const __nv_bfloat16* W3h = EDGE ? g_W13h : g_W3h;
    const __nv_bfloat16* W3l = EDGE ? g_W13l : g_W3l;

    float acc[2][8][4];
    zero_acc(acc);

    // ---------- GEMM1: X[128x384] @ W1t in 3 K-chunks ----------
    for (int c = 0; c < 3; c++) {
        __syncthreads();     // previous chunk's mma reads complete (and idx ready for c=0)
        {
            __nv_bfloat16* Ah = (__nv_bfloat16*)(smA + A_HI);
            __nv_bfloat16* Al = (__nv_bfloat16*)(smA + A_LO);
            for (int u = tid; u < 128 * 32; u += 256) {
                int r = u >> 5, q = u & 31;   // float4 index
                const float* src = (c == 0) ? hVin + (long)gcent[r] * NH
                                 : (c == 1) ? hE + (base + r) * NH
                                            : hVin + (long)gnb[r] * NH;
                float4 v = ((const float4*)src)[q];
                uint32_t h01, l01, h23, l23;
                split2(v.x, v.y, h01, l01);
                split2(v.z, v.w, h23, l23);
                *(uint2*)(Ah + r * LDS_STRIDE + q * 4) = make_uint2(h01, h23);
                *(uint2*)(Al + r * LDS_STRIDE + q * 4) = make_uint2(l01, l23);
            }
        }
        loadB_tile(W1h, W1l, 384, c * 128, smA, tid);
        __syncthreads();
        gemm_chunk(smA, lane, mbase, nbase, acc);
    }
    __syncthreads();

    // ---------- epilogue L1 -> A, load B2 ----------
    epi_gelu_to_A(acc, B1v, smA, lane, mbase, nbase);
    loadB_tile(W2h, W2l, 128, 0, smA, tid);
    __syncthreads();

    // ---------- GEMM2 ----------
    zero_acc(acc);
    gemm_chunk(smA, lane, mbase, nbase, acc);
    __syncthreads();

    // ---------- epilogue L2 -> A, load B3 ----------
    epi_gelu_to_A(acc, B2v, smA, lane, mbase, nbase);
    loadB_tile(W3h, W3l, 128, 0, smA, tid);
    __syncthreads();

    // ---------- GEMM3 ----------
    zero_acc(acc);
    gemm_chunk(smA, lane, mbase, nbase, acc);
    __syncthreads();   // all B reads done before stage aliases B

    // ---------- final epilogue: bias (+mask) -> fp32 stage ----------
    {
        int g = lane >> 2, tig = lane & 3;
        #pragma unroll
        for (int mt = 0; mt < 2; mt++) {
            #pragma unroll
            for (int nt = 0; nt < 8; nt++) {
                int col = nbase + nt * 8 + tig * 2;
                float2 b2 = *(const float2*)(B3v + col);
                int row0 = mbase + mt * 16 + g;
                float2 z0, z1;
                z0.x = (acc[mt][nt][0] + b2.x) * mkr[row0];
                z0.y = (acc[mt][nt][1] + b2.y) * mkr[row0];
                z1.x = (acc[mt][nt][2] + b2.x) * mkr[row0 + 8];
                z1.y = (acc[mt][nt][3] + b2.y) * mkr[row0 + 8];
                *(float2*)(stage + row0 * STG_STRIDE + col) = z0;
                *(float2*)(stage + (row0 + 8) * STG_STRIDE + col) = z1;
            }
        }
    }
    __syncthreads();

    if (!EDGE) {
        // per-node partial sums over rows -> psum slots
        int c = tid & 127, halft = tid >> 7;
        int n0 = (int)(base / NK), n1 = (int)((base + 127) / NK);
        for (int n = n0 + halft; n <= n1; n += 2) {
            int r0 = n * NK - (int)base; if (r0 < 0) r0 = 0;
            int r1 = n * NK + NK - (int)base; if (r1 > 128) r1 = 128;
            float sacc = 0.f;
            for (int r = r0; r < r1; r++) sacc += stage[r * STG_STRIDE + c];
            int slot = (((n * NK) >> 7) == (int)blockIdx.x) ? 0 : 1;
            g_psum[(long)slot * BL * NH + (long)n * NH + c] = sacc;
        }
    } else {
        // per-row residual + LN3 -> h_E out
        float4 sV = ((const float4*)lns)[lane];
        float4 bV = ((const float4*)lnb)[lane];
        #pragma unroll
        for (int i = 0; i < 16; i++) {
            int r = wid * 16 + i;
            long ge = base + r;
            float4 m = ((const float4*)(stage + r * STG_STRIDE))[lane];
            float4 e4 = ((const float4*)(hE + ge * NH))[lane];
            float4 v;
            v.x = e4.x + m.x; v.y = e4.y + m.y; v.z = e4.z + m.z; v.w = e4.w + m.w;
            float mu = warp_sum(v.x + v.y + v.z + v.w) * (1.0f / NH);
            float dx = v.x - mu, dy = v.y - mu, dz = v.z - mu, dw = v.w - mu;
            float var = warp_sum(dx * dx + dy * dy + dz * dz + dw * dw) * (1.0f / NH);
            float inv = rsqrtf(var + LNEPS);
            float4 o;
            o.x = dx * inv * sV.x + bV.x; o.y = dy * inv * sV.y + bV.y;
            o.z = dz * inv * sV.z + bV.z; o.w = dw * inv * sV.w + bV.w;
            ((float4*)(outp + ge * NH))[lane] = o;
        }
    }
}

// ============================ node reduce + LN1 ============================
__global__ void node_reduce(const float* __restrict__ hV, const float* __restrict__ lns,
                            const float* __restrict__ lnb) {
    __shared__ float red[8];
    int n = blockIdx.x, c = threadIdx.x;
    float p = g_psum[(long)n * NH + c];
    if (((n * NK) >> 7) != ((n * NK + NK - 1) >> 7))
        p += g_psum[(long)BL * NH + (long)n * NH + c];
    float h = hV[(long)n * NH + c] + p * SCALE_INV;
    float s = warp_sum(h);
    if ((c & 31) == 0) red[c >> 5] = s;
    __syncthreads();
    float mu = (red[0] + red[1] + red[2] + red[3]) * (1.0f / NH);
    float d = h - mu;
    float q = warp_sum(d * d);
    if ((c & 31) == 0) red[4 + (c >> 5)] = q;
    __syncthreads();
    float var = (red[4] + red[5] + red[6] + red[7]) * (1.0f / NH);
    g_hV1[(long)n * NH + c] = d * rsqrtf(var + LNEPS) * lns[c] + lnb[c];
}

// ============================ FFN (fp32, verified) ============================
__global__ __launch_bounds__(256, 1)
void ffn_kernel(const float* __restrict__ maskV,
                const float* __restrict__ Wi, const float* __restrict__ bi,
                const float* __restrict__ Wo, const float* __restrict__ bo,
                const float* __restrict__ lns, const float* __restrict__ lnb,
                float* __restrict__ out) {
    extern __shared__ float sm[];
    float* Xr = sm;            // [16][128]
    float* Hd = Xr + 16*NH;    // [16][512]
    float* Wc = Hd + 16*512;   // weight staging

    const float* hV1 = g_hV1;
    const int tid = threadIdx.x;
    const long row0 = (long)blockIdx.x * 16;

    for (int t = tid; t < 16*32; t += 256) {
        int r = t >> 5, c = t & 31;
        ((float4*)(Xr + r*NH))[c] = ((const float4*)(hV1 + (row0+r)*NH))[c];
    }
    __syncthreads();

    {
        int cg = tid & 63, rg = tid >> 6;
        float acc[4][8];
        #pragma unroll
        for (int i = 0; i < 4; i++)
            #pragma unroll
            for (int j = 0; j < 8; j++) acc[i][j] = 0.f;
        for (int kk = 0; kk < NH; kk += 16) {
            for (int u = tid; u < 16*128; u += 256) {
                int wr = u >> 7, wc = u & 127;
                ((float4*)(Wc + wr*512))[wc] = ((const float4*)(Wi + (long)(kk+wr)*512))[wc];
            }
            __syncthreads();
            #pragma unroll
            for (int k = 0; k < 16; k++) {
                float4 w0 = ((const float4*)(Wc + k*512))[cg*2];
                float4 w1 = ((const float4*)(Wc + k*512))[cg*2+1];
                #pragma unroll
                for (int i = 0; i < 4; i++) {
                    float x = Xr[(rg*4+i)*NH + kk + k];
                    acc[i][0]+=x*w0.x; acc[i][1]+=x*w0.y; acc[i][2]+=x*w0.z; acc[i][3]+=x*w0.w;
                    acc[i][4]+=x*w1.x; acc[i][5]+=x*w1.y; acc[i][6]+=x*w1.z; acc[i][7]+=x*w1.w;
                }
            }
            __syncthreads();
        }
        float4 b0 = ((const float4*)bi)[cg*2];
        float4 b1 = ((const float4*)bi)[cg*2+1];
        #pragma unroll
        for (int i = 0; i < 4; i++) {
            int r = rg*4 + i;
            float4 o0, o1;
            o0.x = gelu_f(acc[i][0]+b0.x); o0.y = gelu_f(acc[i][1]+b0.y);
            o0.z = gelu_f(acc[i][2]+b0.z); o0.w = gelu_f(acc[i][3]+b0.w);
            o1.x = gelu_f(acc[i][4]+b1.x); o1.y = gelu_f(acc[i][5]+b1.y);
            o1.z = gelu_f(acc[i][6]+b1.z); o1.w = gelu_f(acc[i][7]+b1.w);
            ((float4*)(Hd + r*512))[cg*2]   = o0;
            ((float4*)(Hd + r*512))[cg*2+1] = o1;
        }
    }
    __syncthreads();

    {
        int cg = tid & 63, rg = tid >> 6;
        float acc[4][2];
        #pragma unroll
        for (int i = 0; i < 4; i++) { acc[i][0]=0.f; acc[i][1]=0.f; }
        for (int kk = 0; kk < 512; kk += 32) {
            for (int u = tid; u < 32*32; u += 256) {
                int wr = u >> 5, wc = u & 31;
                ((float4*)(Wc + wr*NH))[wc] = ((const float4*)(Wo + (long)(kk+wr)*NH))[wc];
            }
            __syncthreads();
            #pragma unroll
            for (int k = 0; k < 32; k++) {
                float2 w = ((const float2*)(Wc + k*NH))[cg];
                #pragma unroll
                for (int i = 0; i < 4; i++) {
                    float x = Hd[(rg*4+i)*512 + kk + k];
                    acc[i][0] += x*w.x; acc[i][1] += x*w.y;
                }
            }
            __syncthreads();
        }
        float2 bv = ((const float2*)bo)[cg];
        #pragma unroll
        for (int i = 0; i < 4; i++) {
            int r = rg*4 + i;
            float2 z;
            z.x = acc[i][0] + bv.x + Xr[r*NH + cg*2];
            z.y = acc[i][1] + bv.y + Xr[r*NH + cg*2 + 1];
            ((float2*)(Hd + r*NH))[cg] = z;
        }
    }
    __syncthreads();

    {
        int wid = tid >> 5, lane = tid & 31;
        float4 sV = ((const float4*)lns)[lane];
        float4 bV = ((const float4*)lnb)[lane];
        #pragma unroll
        for (int rr = 0; rr < 2; rr++) {
            int r = wid*2 + rr;
            long grow = row0 + r;
            float mk = maskV[grow];
            float4 v = ((const float4*)(Hd + r*NH))[lane];
            float mu = warp_sum(v.x+v.y+v.z+v.w) * (1.0f/NH);
            float dx=v.x-mu, dy=v.y-mu, dz=v.z-mu, dw=v.w-mu;
            float var = warp_sum(dx*dx+dy*dy+dz*dz+dw*dw) * (1.0f/NH);
            float inv = rsqrtf(var + LNEPS);
            float4 o;
            o.x = (dx*inv*sV.x + bV.x)*mk; o.y = (dy*inv*sV.y + bV.y)*mk;
            o.z = (dz*inv*sV.z + bV.z)*mk; o.w = (dw*inv*sV.w + bV.w)*mk;
            ((float4*)(out + grow*NH))[lane] = o;
        }
    }
}

// ============================ host ============================
extern "C" void kernel_launch(void* const* d_in, const int* in_sizes, int n_in,
                              void* d_out, int out_size) {
    (void)in_sizes; (void)n_in; (void)out_size;
    const float* hV    = (const float*)d_in[0];
    const float* hE    = (const float*)d_in[1];
    const int*   Eidx  = (const int*)d_in[2];
    const float* maskV = (const float*)d_in[3];
    const float* maskA = (const float*)d_in[4];
    const float *W1 =(const float*)d_in[5],  *b1 =(const float*)d_in[6];
    const float *W2 =(const float*)d_in[7],  *b2 =(const float*)d_in[8];
    const float *W3 =(const float*)d_in[9],  *b3 =(const float*)d_in[10];
    const float *W11=(const float*)d_in[11], *b11=(const float*)d_in[12];
    const float *W12=(const float*)d_in[13], *b12=(const float*)d_in[14];
    const float *W13=(const float*)d_in[15], *b13=(const float*)d_in[16];
    const float *Wi =(const float*)d_in[17], *bi =(const float*)d_in[18];
    const float *Wo =(const float*)d_in[19], *bo =(const float*)d_in[20];
    const float *ln1s=(const float*)d_in[21], *ln1b=(const float*)d_in[22];
    const float *ln2s=(const float*)d_in[23], *ln2b=(const float*)d_in[24];
    const float *ln3s=(const float*)d_in[25], *ln3b=(const float*)d_in[26];

    float* outV = (float*)d_out;
    float* outE = outV + (long)BL*NH;

    cudaFuncSetAttribute(mma_stage<false>, cudaFuncAttributeMaxDynamicSharedMemorySize, DSMEM_TOTAL);
    cudaFuncSetAttribute(mma_stage<true>,  cudaFuncAttributeMaxDynamicSharedMemorySize, DSMEM_TOTAL);
    const int sm2 = (16*NH + 16*512 + 16*512) * (int)sizeof(float);
    cudaFuncSetAttribute(ffn_kernel, cudaFuncAttributeMaxDynamicSharedMemorySize, sm2);

    prep_weights<<<96, 256>>>(W1, W2, W3, W11, W12, W13);
    mma_stage<false><<<NTILE, 256, DSMEM_TOTAL>>>(hV, hE, Eidx, maskA,
                                                  b1, b2, b3, nullptr, nullptr, nullptr);
    node_reduce<<<BL, 128>>>(hV, ln1s, ln1b);
    ffn_kernel<<<BL/16, 256, sm2>>>(maskV, Wi, bi, Wo, bo, ln2s, ln2b, outV);
    mma_stage<true><<<NTILE, 256, DSMEM_TOTAL>>>(outV, hE, Eidx, maskA,
                                                 b11, b12, b13, ln3s, ln3b, outE);
}

// round 5
// speedup vs baseline: 2.9585x; 1.4599x over previous
#include <cuda_runtime.h>
#include <cuda_bf16.h>
#include <math.h>
#include <stdint.h>

#define NB 2
#define NL 2048
#define NK 48
#define NH 128
#define BL (NB*NL)              // 4096
#define NEDGE (BL*NK)           // 196608
#define NTILE (NEDGE/128)       // 1536
#define SCALE_INV (1.0f/30.0f)
#define LNEPS 1e-5f

#define NTHREADS 512

// padded smem row stride (bf16 elements): 136*2 = 272B -> conflict-free ldmatrix
#define LDS_STRIDE 136
// byte offsets inside the 1024-aligned dynamic smem block
#define A_HI 0
#define A_LO 34816                    // 128*136*2
#define BUF0 69632                    // B buffer 0 (hi at +0, lo at +34816)
#define BUF1 139264                   // B buffer 1
#define BLO_OFF 34816
#define SM_BYTES 208896
#define DSMEM_TOTAL (SM_BYTES + 1024)
// fp32 stage buffer aliases BUF1 region; padded stride 132 floats
#define STG_STRIDE 132

// ---- transposed + hi/lo split weights (K-major [N=128][Ktot]) ----
__device__ __align__(16) __nv_bfloat16 g_W1h[128*384],  g_W1l[128*384];
__device__ __align__(16) __nv_bfloat16 g_W2h[128*128],  g_W2l[128*128];
__device__ __align__(16) __nv_bfloat16 g_W3h[128*128],  g_W3l[128*128];
__device__ __align__(16) __nv_bfloat16 g_W11h[128*384], g_W11l[128*384];
__device__ __align__(16) __nv_bfloat16 g_W12h[128*128], g_W12l[128*128];
__device__ __align__(16) __nv_bfloat16 g_W13h[128*128], g_W13l[128*128];
__device__ float g_psum[2L*BL*NH];       // 2 slots per node
__device__ float g_hV1[(long)BL*NH];

// ============================ helpers ============================
__device__ __forceinline__ uint32_t smem_u32(const void* p) {
    uint32_t a;
    asm("{ .reg .u64 t; cvta.to.shared.u64 t, %1; cvt.u32.u64 %0, t; }" : "=r"(a) : "l"(p));
    return a;
}
__device__ __forceinline__ void ldsm_x4(uint32_t* r, uint32_t addr) {
    asm volatile("ldmatrix.sync.aligned.m8n8.x4.shared.b16 {%0,%1,%2,%3}, [%4];"
        : "=r"(r[0]), "=r"(r[1]), "=r"(r[2]), "=r"(r[3]) : "r"(addr));
}
__device__ __forceinline__ void mma16816(float* d, const uint32_t* a, const uint32_t* b) {
    asm volatile("mma.sync.aligned.m16n8k16.row.col.f32.bf16.bf16.f32 "
        "{%0,%1,%2,%3}, {%4,%5,%6,%7}, {%8,%9}, {%0,%1,%2,%3};"
        : "+f"(d[0]), "+f"(d[1]), "+f"(d[2]), "+f"(d[3])
        : "r"(a[0]), "r"(a[1]), "r"(a[2]), "r"(a[3]), "r"(b[0]), "r"(b[1]));
}
#define CP_ASYNC16(dst, src) \
    asm volatile("cp.async.cg.shared.global [%0], [%1], 16;" :: "r"(dst), "l"(src))
#define CP_COMMIT() asm volatile("cp.async.commit_group;" ::: "memory")
#define CP_WAIT0()  asm volatile("cp.async.wait_group 0;" ::: "memory")

__device__ __forceinline__ float gelu_f(float x) {
    return 0.5f * x * (1.0f + erff(x * 0.70710678118654752f));
}
__device__ __forceinline__ float warp_sum(float v) {
    #pragma unroll
    for (int o = 16; o > 0; o >>= 1) v += __shfl_xor_sync(0xffffffffu, v, o);
    return v;
}
// split x,y to packed hi-bf16x2 and lo-bf16x2
__device__ __forceinline__ void split2(float x, float y, uint32_t& hp, uint32_t& lp) {
    __nv_bfloat16 hx = __float2bfloat16(x), hy = __float2bfloat16(y);
    float lx = x - __bfloat162float(hx), ly = y - __bfloat162float(hy);
    hp = ((uint32_t)__bfloat16_as_ushort(hy) << 16) | __bfloat16_as_ushort(hx);
    __nv_bfloat16 lbx = __float2bfloat16(lx), lby = __float2bfloat16(ly);
    lp = ((uint32_t)__bfloat16_as_ushort(lby) << 16) | __bfloat16_as_ushort(lbx);
}

// ============================ prep: transpose + split weights ============================
template<int K>
__device__ __forceinline__ void split_tr(const float* __restrict__ W, __nv_bfloat16* H,
                                         __nv_bfloat16* L, int g, int gs) {
    for (int i = g; i < K * 128; i += gs) {
        int n = i / K, k = i - n * K;            // write-coalesced over k
        float v = W[(long)k * 128 + n];
        __nv_bfloat16 h = __float2bfloat16(v);
        float lo = v - __bfloat162float(h);
        H[(long)n * K + k] = h;
        L[(long)n * K + k] = __float2bfloat16(lo);
    }
}
__global__ void prep_weights(const float* W1, const float* W2, const float* W3,
                             const float* W11, const float* W12, const float* W13) {
    int g = blockIdx.x * blockDim.x + threadIdx.x;
    int gs = gridDim.x * blockDim.x;
    split_tr<384>(W1,  g_W1h,  g_W1l,  g, gs);
    split_tr<128>(W2,  g_W2h,  g_W2l,  g, gs);
    split_tr<128>(W3,  g_W3h,  g_W3l,  g, gs);
    split_tr<384>(W11, g_W11h, g_W11l, g, gs);
    split_tr<128>(W12, g_W12h, g_W12l, g, gs);
    split_tr<128>(W13, g_W13h, g_W13l, g, gs);
}

// ============================ MMA stage ============================
// async B load: 128 rows x 128 bf16 (hi+lo), each row = 16 x 16B segments
__device__ __forceinline__ void asyncB(const __nv_bfloat16* __restrict__ Wh,
                                       const __nv_bfloat16* __restrict__ Wl,
                                       int Ktot, int kk, uint32_t bufAddr, int tid) {
    #pragma unroll
    for (int u = tid; u < 2048; u += NTHREADS) {
        int n = u >> 4, s = u & 15;
        uint32_t dst = bufAddr + n * (LDS_STRIDE * 2) + s * 16;
        CP_ASYNC16(dst, (const char*)(Wh + (long)n * Ktot + kk) + s * 16);
        CP_ASYNC16(dst + BLO_OFF, (const char*)(Wl + (long)n * Ktot + kk) + s * 16);
    }
    CP_COMMIT();
}

// one 128-K chunk of MMA: 8 k-steps, 3-combo hi/lo split. acc[8][4].
__device__ __forceinline__ void gemm_chunk(uint32_t sb, uint32_t bbase, int lane,
                                           int mbase, int nbase, float acc[8][4]) {
    // A lane address (x4): row = mbase + (lane&15), col = (lane>>4)*8
    const uint32_t aOff = (uint32_t)(((mbase + (lane & 15)) * LDS_STRIDE + ((lane >> 4) << 3)) * 2);
    // B lane address (x4 covering 2 n-tiles): row = nbase + p*16 + ((lane>>4)&1)*8 + (lane&7),
    //                                         col = ((lane>>3)&1)*8
    const int bRow0 = nbase + ((lane >> 4) & 1) * 8 + (lane & 7);
    const int bCol  = ((lane >> 3) & 1) * 8;

    #pragma unroll
    for (int ks = 0; ks < 8; ks++) {
        const uint32_t k0b = ks * 32;   // 16 bf16 = 32 bytes
        uint32_t ah[4], al[4];
        ldsm_x4(ah, sb + A_HI + aOff + k0b);
        ldsm_x4(al, sb + A_LO + aOff + k0b);
        uint32_t bh[4][4], blr[4][4];
        #pragma unroll
        for (int p = 0; p < 4; p++) {
            uint32_t ba = (uint32_t)(((bRow0 + p * 16) * LDS_STRIDE + bCol) * 2) + k0b;
            ldsm_x4(bh[p],  bbase + ba);
            ldsm_x4(blr[p], bbase + BLO_OFF + ba);
        }
        #pragma unroll
        for (int nt = 0; nt < 8; nt++) {
            const uint32_t* fh = &bh[nt >> 1][(nt & 1) * 2];
            const uint32_t* fl = &blr[nt >> 1][(nt & 1) * 2];
            mma16816(acc[nt], ah, fh);
            mma16816(acc[nt], ah, fl);
            mma16816(acc[nt], al, fh);
        }
    }
}

__device__ __forceinline__ void zero_acc(float acc[8][4]) {
    #pragma unroll
    for (int nt = 0; nt < 8; nt++)
        #pragma unroll
        for (int j = 0; j < 4; j++) acc[nt][j] = 0.f;
}

// bias + gelu + hi/lo split back into A smem (warp tile 16 rows x 64 cols)
__device__ __forceinline__ void epi_gelu_to_A(float acc[8][4], const float* __restrict__ bias,
                                              char* smA, int lane, int mbase, int nbase) {
    __nv_bfloat16* Ah = (__nv_bfloat16*)(smA + A_HI);
    __nv_bfloat16* Al = (__nv_bfloat16*)(smA + A_LO);
    int g = lane >> 2, tig = lane & 3;
    #pragma unroll
    for (int nt = 0; nt < 8; nt++) {
        int col = nbase + nt * 8 + tig * 2;
        float2 b2 = *(const float2*)(bias + col);
        float x0 = gelu_f(acc[nt][0] + b2.x);
        float x1 = gelu_f(acc[nt][1] + b2.y);
        float x2 = gelu_f(acc[nt][2] + b2.x);
        float x3 = gelu_f(acc[nt][3] + b2.y);
        int row0 = mbase + g;
        uint32_t hp, lp;
        split2(x0, x1, hp, lp);
        *(uint32_t*)(Ah + row0 * LDS_STRIDE + col) = hp;
        *(uint32_t*)(Al + row0 * LDS_STRIDE + col) = lp;
        split2(x2, x3, hp, lp);
        *(uint32_t*)(Ah + (row0 + 8) * LDS_STRIDE + col) = hp;
        *(uint32_t*)(Al + (row0 + 8) * LDS_STRIDE + col) = lp;
    }
}

template<bool EDGE>
__global__ __launch_bounds__(NTHREADS, 1)
void mma_stage(const float* __restrict__ hVin,
               const float* __restrict__ hE,
               const int* __restrict__ Eidx,
               const float* __restrict__ maskA,
               const float* __restrict__ B1v, const float* __restrict__ B2v,
               const float* __restrict__ B3v,
               const float* __restrict__ lns, const float* __restrict__ lnb,
               float* __restrict__ outp) {
    extern __shared__ char dsm[];
    char* smA = (char*)(((uintptr_t)dsm + 1023) & ~(uintptr_t)1023);
    float* stage = (float*)(smA + BUF1);          // aliases BUF1 (last MMA uses BUF0)

    __shared__ int   gcent[128];
    __shared__ int   gnb[128];
    __shared__ float mkr[128];

    const int tid = threadIdx.x, wid = tid >> 5, lane = tid & 31;
    const long base = (long)blockIdx.x * 128;
    const int mbase = (wid & 7) * 16;
    const int nbase = (wid >> 3) * 64;
    const uint32_t sb = smem_u32(smA);

    const __nv_bfloat16* W1h = EDGE ? g_W11h : g_W1h;
    const __nv_bfloat16* W1l = EDGE ? g_W11l : g_W1l;
    const __nv_bfloat16* W2h = EDGE ? g_W12h : g_W2h;
    const __nv_bfloat16* W2l = EDGE ? g_W12l : g_W2l;
    const __nv_bfloat16* W3h = EDGE ? g_W13h : g_W3h;
    const __nv_bfloat16* W3l = EDGE ? g_W13l : g_W3l;

    // kick off B chunk0 load immediately
    asyncB(W1h, W1l, 384, 0, sb + BUF0, tid);

    if (tid < 128) {
        long e = base + tid;
        int n = (int)(e / NK);
        gcent[tid] = n;
        gnb[tid] = (n >> 11) * NL + Eidx[e];
        if (!EDGE) mkr[tid] = maskA[e]; else mkr[tid] = 1.f;
    }
    __syncthreads();

    float acc[8][4];
    zero_acc(acc);

    // ---------- GEMM1: X[128x384] @ W1t in 3 K-chunks, double-buffered B ----------
    #pragma unroll 1
    for (int c = 0; c < 3; c++) {
        // build A chunk c: c0=center hV, c1=hE, c2=neighbor hV
        {
            __nv_bfloat16* Ah = (__nv_bfloat16*)(smA + A_HI);
            __nv_bfloat16* Al = (__nv_bfloat16*)(smA + A_LO);
            #pragma unroll
            for (int u = tid; u < 128 * 32; u += NTHREADS) {
                int r = u >> 5, q = u & 31;   // float4 index
                const float* src = (c == 0) ? hVin + (long)gcent[r] * NH
                                 : (c == 1) ? hE + (base + r) * NH
                                            : hVin + (long)gnb[r] * NH;
                float4 v = ((const float4*)src)[q];
                uint32_t h01, l01, h23, l23;
                split2(v.x, v.y, h01, l01);
                split2(v.z, v.w, h23, l23);
                *(uint2*)(Ah + r * LDS_STRIDE + q * 4) = make_uint2(h01, h23);
                *(uint2*)(Al + r * LDS_STRIDE + q * 4) = make_uint2(l01, l23);
            }
        }
        CP_WAIT0();
        __syncthreads();
        // prefetch next B into alternate buffer while this chunk's MMA runs
        uint32_t cur = (c & 1) ? BUF1 : BUF0;
        uint32_t nxt = (c & 1) ? BUF0 : BUF1;
        if (c < 2)      asyncB(W1h, W1l, 384, (c + 1) * 128, sb + nxt, tid);
        else            asyncB(W2h, W2l, 128, 0, sb + nxt, tid);   // -> BUF1
        gemm_chunk(sb, sb + cur, lane, mbase, nbase, acc);
        __syncthreads();
    }

    // ---------- epilogue L1 -> A (B2 already in flight into BUF1) ----------
    epi_gelu_to_A(acc, B1v, smA, lane, mbase, nbase);
    CP_WAIT0();
    __syncthreads();

    // ---------- GEMM2 (BUF1), prefetch B3 -> BUF0 ----------
    asyncB(W3h, W3l, 128, 0, sb + BUF0, tid);
    zero_acc(acc);
    gemm_chunk(sb, sb + BUF1, lane, mbase, nbase, acc);
    __syncthreads();

    // ---------- epilogue L2 -> A ----------
    epi_gelu_to_A(acc, B2v, smA, lane, mbase, nbase);
    CP_WAIT0();
    __syncthreads();

    // ---------- GEMM3 (BUF0) ----------
    zero_acc(acc);
    gemm_chunk(sb, sb + BUF0, lane, mbase, nbase, acc);
    __syncthreads();   // BUF1 free -> stage may alias it

    // ---------- final epilogue: bias (+mask) -> fp32 stage ----------
    {
        int g = lane >> 2, tig = lane & 3;
        #pragma unroll
        for (int nt = 0; nt < 8; nt++) {
            int col = nbase + nt * 8 + tig * 2;
            float2 b2 = *(const float2*)(B3v + col);
            int row0 = mbase + g;
            float2 z0, z1;
            z0.x = (acc[nt][0] + b2.x) * mkr[row0];
            z0.y = (acc[nt][1] + b2.y) * mkr[row0];
            z1.x = (acc[nt][2] + b2.x) * mkr[row0 + 8];
            z1.y = (acc[nt][3] + b2.y) * mkr[row0 + 8];
            *(float2*)(stage + row0 * STG_STRIDE + col) = z0;
            *(float2*)(stage + (row0 + 8) * STG_STRIDE + col) = z1;
        }
    }
    __syncthreads();

    if (!EDGE) {
        // per-node partial sums over rows -> psum slots (<=4 nodes per tile)
        int c = tid & 127, quarter = tid >> 7;   // 0..3
        int n0 = (int)(base / NK), n1 = (int)((base + 127) / NK);
        for (int n = n0 + quarter; n <= n1; n += 4) {
            int r0 = n * NK - (int)base; if (r0 < 0) r0 = 0;
            int r1 = n * NK + NK - (int)base; if (r1 > 128) r1 = 128;
            float sacc = 0.f;
            for (int r = r0; r < r1; r++) sacc += stage[r * STG_STRIDE + c];
            int slot = (((n * NK) >> 7) == (int)blockIdx.x) ? 0 : 1;
            g_psum[(long)slot * BL * NH + (long)n * NH + c] = sacc;
        }
    } else {
        // per-row residual + LN3 -> h_E out (16 warps x 8 rows)
        float4 sV = ((const float4*)lns)[lane];
        float4 bV = ((const float4*)lnb)[lane];
        #pragma unroll
        for (int i = 0; i < 8; i++) {
            int r = wid * 8 + i;
            long ge = base + r;
            float4 m = ((const float4*)(stage + r * STG_STRIDE))[lane];
            float4 e4 = ((const float4*)(hE + ge * NH))[lane];
            float4 v;
            v.x = e4.x + m.x; v.y = e4.y + m.y; v.z = e4.z + m.z; v.w = e4.w + m.w;
            float mu = warp_sum(v.x + v.y + v.z + v.w) * (1.0f / NH);
            float dx = v.x - mu, dy = v.y - mu, dz = v.z - mu, dw = v.w - mu;
            float var = warp_sum(dx * dx + dy * dy + dz * dz + dw * dw) * (1.0f / NH);
            float inv = rsqrtf(var + LNEPS);
            float4 o;
            o.x = dx * inv * sV.x + bV.x; o.y = dy * inv * sV.y + bV.y;
            o.z = dz * inv * sV.z + bV.z; o.w = dw * inv * sV.w + bV.w;
            ((float4*)(outp + ge * NH))[lane] = o;
        }
    }
}

// ============================ node reduce + LN1 ============================
__global__ void node_reduce(const float* __restrict__ hV, const float* __restrict__ lns,
                            const float* __restrict__ lnb) {
    __shared__ float red[8];
    int n = blockIdx.x, c = threadIdx.x;
    float p = g_psum[(long)n * NH + c];
    if (((n * NK) >> 7) != ((n * NK + NK - 1) >> 7))
        p += g_psum[(long)BL * NH + (long)n * NH + c];
    float h = hV[(long)n * NH + c] + p * SCALE_INV;
    float s = warp_sum(h);
    if ((c & 31) == 0) red[c >> 5] = s;
    __syncthreads();
    float mu = (red[0] + red[1] + red[2] + red[3]) * (1.0f / NH);
    float d = h - mu;
    float q = warp_sum(d * d);
    if ((c & 31) == 0) red[4 + (c >> 5)] = q;
    __syncthreads();
    float var = (red[4] + red[5] + red[6] + red[7]) * (1.0f / NH);
    g_hV1[(long)n * NH + c] = d * rsqrtf(var + LNEPS) * lns[c] + lnb[c];
}

// ============================ FFN (fp32, verified) ============================
__global__ __launch_bounds__(256, 1)
void ffn_kernel(const float* __restrict__ maskV,
                const float* __restrict__ Wi, const float* __restrict__ bi,
                const float* __restrict__ Wo, const float* __restrict__ bo,
                const float* __restrict__ lns, const float* __restrict__ lnb,
                float* __restrict__ out) {
    extern __shared__ float sm[];
    float* Xr = sm;            // [16][128]
    float* Hd = Xr + 16*NH;    // [16][512]
    float* Wc = Hd + 16*512;   // weight staging

    const float* hV1 = g_hV1;
    const int tid = threadIdx.x;
    const long row0 = (long)blockIdx.x * 16;

    for (int t = tid; t < 16*32; t += 256) {
        int r = t >> 5, c = t & 31;
        ((float4*)(Xr + r*NH))[c] = ((const float4*)(hV1 + (row0+r)*NH))[c];
    }
    __syncthreads();

    {
        int cg = tid & 63, rg = tid >> 6;
        float acc[4][8];
        #pragma unroll
        for (int i = 0; i < 4; i++)
            #pragma unroll
            for (int j = 0; j < 8; j++) acc[i][j] = 0.f;
        for (int kk = 0; kk < NH; kk += 16) {
            for (int u = tid; u < 16*128; u += 256) {
                int wr = u >> 7, wc = u & 127;
                ((float4*)(Wc + wr*512))[wc] = ((const float4*)(Wi + (long)(kk+wr)*512))[wc];
            }
            __syncthreads();
            #pragma unroll
            for (int k = 0; k < 16; k++) {
                float4 w0 = ((const float4*)(Wc + k*512))[cg*2];
                float4 w1 = ((const float4*)(Wc + k*512))[cg*2+1];
                #pragma unroll
                for (int i = 0; i < 4; i++) {
                    float x = Xr[(rg*4+i)*NH + kk + k];
                    acc[i][0]+=x*w0.x; acc[i][1]+=x*w0.y; acc[i][2]+=x*w0.z; acc[i][3]+=x*w0.w;
                    acc[i][4]+=x*w1.x; acc[i][5]+=x*w1.y; acc[i][6]+=x*w1.z; acc[i][7]+=x*w1.w;
                }
            }
            __syncthreads();
        }
        float4 b0 = ((const float4*)bi)[cg*2];
        float4 b1 = ((const float4*)bi)[cg*2+1];
        #pragma unroll
        for (int i = 0; i < 4; i++) {
            int r = rg*4 + i;
            float4 o0, o1;
            o0.x = gelu_f(acc[i][0]+b0.x); o0.y = gelu_f(acc[i][1]+b0.y);
            o0.z = gelu_f(acc[i][2]+b0.z); o0.w = gelu_f(acc[i][3]+b0.w);
            o1.x = gelu_f(acc[i][4]+b1.x); o1.y = gelu_f(acc[i][5]+b1.y);
            o1.z = gelu_f(acc[i][6]+b1.z); o1.w = gelu_f(acc[i][7]+b1.w);
            ((float4*)(Hd + r*512))[cg*2]   = o0;
            ((float4*)(Hd + r*512))[cg*2+1] = o1;
        }
    }
    __syncthreads();

    {
        int cg = tid & 63, rg = tid >> 6;
        float acc[4][2];
        #pragma unroll
        for (int i = 0; i < 4; i++) { acc[i][0]=0.f; acc[i][1]=0.f; }
        for (int kk = 0; kk < 512; kk += 32) {
            for (int u = tid; u < 32*32; u += 256) {
                int wr = u >> 5, wc = u & 31;
                ((float4*)(Wc + wr*NH))[wc] = ((const float4*)(Wo + (long)(kk+wr)*NH))[wc];
            }
            __syncthreads();
            #pragma unroll
            for (int k = 0; k < 32; k++) {
                float2 w = ((const float2*)(Wc + k*NH))[cg];
                #pragma unroll
                for (int i = 0; i < 4; i++) {
                    float x = Hd[(rg*4+i)*512 + kk + k];
                    acc[i][0] += x*w.x; acc[i][1] += x*w.y;
                }
            }
            __syncthreads();
        }
        float2 bv = ((const float2*)bo)[cg];
        #pragma unroll
        for (int i = 0; i < 4; i++) {
            int r = rg*4 + i;
            float2 z;
            z.x = acc[i][0] + bv.x + Xr[r*NH + cg*2];
            z.y = acc[i][1] + bv.y + Xr[r*NH + cg*2 + 1];
            ((float2*)(Hd + r*NH))[cg] = z;
        }
    }
    __syncthreads();

    {
        int wid = tid >> 5, lane = tid & 31;
        float4 sV = ((const float4*)lns)[lane];
        float4 bV = ((const float4*)lnb)[lane];
        #pragma unroll
        for (int rr = 0; rr < 2; rr++) {
            int r = wid*2 + rr;
            long grow = row0 + r;
            float mk = maskV[grow];
            float4 v = ((const float4*)(Hd + r*NH))[lane];
            float mu = warp_sum(v.x+v.y+v.z+v.w) * (1.0f/NH);
            float dx=v.x-mu, dy=v.y-mu, dz=v.z-mu, dw=v.w-mu;
            float var = warp_sum(dx*dx+dy*dy+dz*dz+dw*dw) * (1.0f/NH);
            float inv = rsqrtf(var + LNEPS);
            float4 o;
            o.x = (dx*inv*sV.x + bV.x)*mk; o.y = (dy*inv*sV.y + bV.y)*mk;
            o.z = (dz*inv*sV.z + bV.z)*mk; o.w = (dw*inv*sV.w + bV.w)*mk;
            ((float4*)(out + grow*NH))[lane] = o;
        }
    }
}

// ============================ host ============================
extern "C" void kernel_launch(void* const* d_in, const int* in_sizes, int n_in,
                              void* d_out, int out_size) {
    (void)in_sizes; (void)n_in; (void)out_size;
    const float* hV    = (const float*)d_in[0];
    const float* hE    = (const float*)d_in[1];
    const int*   Eidx  = (const int*)d_in[2];
    const float* maskV = (const float*)d_in[3];
    const float* maskA = (const float*)d_in[4];
    const float *W1 =(const float*)d_in[5],  *b1 =(const float*)d_in[6];
    const float *W2 =(const float*)d_in[7],  *b2 =(const float*)d_in[8];
    const float *W3 =(const float*)d_in[9],  *b3 =(const float*)d_in[10];
    const float *W11=(const float*)d_in[11], *b11=(const float*)d_in[12];
    const float *W12=(const float*)d_in[13], *b12=(const float*)d_in[14];
    const float *W13=(const float*)d_in[15], *b13=(const float*)d_in[16];
    const float *Wi =(const float*)d_in[17], *bi =(const float*)d_in[18];
    const float *Wo =(const float*)d_in[19], *bo =(const float*)d_in[20];
    const float *ln1s=(const float*)d_in[21], *ln1b=(const float*)d_in[22];
    const float *ln2s=(const float*)d_in[23], *ln2b=(const float*)d_in[24];
    const float *ln3s=(const float*)d_in[25], *ln3b=(const float*)d_in[26];

    float* outV = (float*)d_out;
    float* outE = outV + (long)BL*NH;

    cudaFuncSetAttribute(mma_stage<false>, cudaFuncAttributeMaxDynamicSharedMemorySize, DSMEM_TOTAL);
    cudaFuncSetAttribute(mma_stage<true>,  cudaFuncAttributeMaxDynamicSharedMemorySize, DSMEM_TOTAL);
    const int sm2 = (16*NH + 16*512 + 16*512) * (int)sizeof(float);
    cudaFuncSetAttribute(ffn_kernel, cudaFuncAttributeMaxDynamicSharedMemorySize, sm2);

    prep_weights<<<148, 256>>>(W1, W2, W3, W11, W12, W13);
    mma_stage<false><<<NTILE, NTHREADS, DSMEM_TOTAL>>>(hV, hE, Eidx, maskA,
                                                       b1, b2, b3, nullptr, nullptr, nullptr);
    node_reduce<<<BL, 128>>>(hV, ln1s, ln1b);
    ffn_kernel<<<BL/16, 256, sm2>>>(maskV, Wi, bi, Wo, bo, ln2s, ln2b, outV);
    mma_stage<true><<<NTILE, NTHREADS, DSMEM_TOTAL>>>(outV, hE, Eidx, maskA,
                                                      b11, b12, b13, ln3s, ln3b, outE);
}

// round 7
// speedup vs baseline: 4.3566x; 1.4725x over previous
#include <cuda_runtime.h>
#include <cuda_bf16.h>
#include <math.h>
#include <stdint.h>

#define NB 2
#define NL 2048
#define NK 48
#define NH 128
#define BL (NB*NL)              // 4096
#define NEDGE (BL*NK)           // 196608
#define NTILE (NEDGE/128)       // 1536
#define SCALE_INV (1.0f/30.0f)
#define LNEPS 1e-5f

#define NTHREADS 512

// padded smem row stride (bf16 elements): 136*2 = 272B -> conflict-free ldmatrix
#define LDS_STRIDE 136
#define A_HI 0
#define A_LO 34816                    // 128*136*2
#define BUF0 69632                    // B buffer 0 (hi at +0, lo at +34816)
#define BUF1 139264                   // B buffer 1
#define BLO_OFF 34816
#define SM_BYTES 208896
#define DSMEM_TOTAL (SM_BYTES + 1024)
#define STG_STRIDE 132

// ---- transposed + hi/lo split weights (K-major [N=128][Ktot]) ----
__device__ __align__(16) __nv_bfloat16 g_W1h[128*384],  g_W1l[128*384];
__device__ __align__(16) __nv_bfloat16 g_W2h[128*128],  g_W2l[128*128];
__device__ __align__(16) __nv_bfloat16 g_W3h[128*128],  g_W3l[128*128];
__device__ __align__(16) __nv_bfloat16 g_W11h[128*384], g_W11l[128*384];
__device__ __align__(16) __nv_bfloat16 g_W12h[128*128], g_W12l[128*128];
__device__ __align__(16) __nv_bfloat16 g_W13h[128*128], g_W13l[128*128];
__device__ float g_psum[2L*BL*NH];       // 2 slots per node
__device__ float g_hV1[(long)BL*NH];
__device__ float g_Pa[(long)BL*NH];      // node precomp: hV @ W1a
__device__ float g_Pc[(long)BL*NH];      // node precomp: hV @ W1c

// ============================ helpers ============================
__device__ __forceinline__ uint32_t smem_u32(const void* p) {
    uint32_t a;
    asm("{ .reg .u64 t; cvta.to.shared.u64 t, %1; cvt.u32.u64 %0, t; }" : "=r"(a) : "l"(p));
    return a;
}
__device__ __forceinline__ void ldsm_x4(uint32_t* r, uint32_t addr) {
    asm volatile("ldmatrix.sync.aligned.m8n8.x4.shared.b16 {%0,%1,%2,%3}, [%4];"
        : "=r"(r[0]), "=r"(r[1]), "=r"(r[2]), "=r"(r[3]) : "r"(addr));
}
__device__ __forceinline__ void mma16816(float* d, const uint32_t* a, const uint32_t* b) {
    asm volatile("mma.sync.aligned.m16n8k16.row.col.f32.bf16.bf16.f32 "
        "{%0,%1,%2,%3}, {%4,%5,%6,%7}, {%8,%9}, {%0,%1,%2,%3};"
        : "+f"(d[0]), "+f"(d[1]), "+f"(d[2]), "+f"(d[3])
        : "r"(a[0]), "r"(a[1]), "r"(a[2]), "r"(a[3]), "r"(b[0]), "r"(b[1]));
}
#define CP_ASYNC16(dst, src) \
    asm volatile("cp.async.cg.shared.global [%0], [%1], 16;" :: "r"(dst), "l"(src))
#define CP_COMMIT() asm volatile("cp.async.commit_group;" ::: "memory")
#define CP_WAIT0()  asm volatile("cp.async.wait_group 0;" ::: "memory")

__device__ __forceinline__ float gelu_f(float x) {
    return 0.5f * x * (1.0f + erff(x * 0.70710678118654752f));
}
__device__ __forceinline__ float warp_sum(float v) {
    #pragma unroll
    for (int o = 16; o > 0; o >>= 1) v += __shfl_xor_sync(0xffffffffu, v, o);
    return v;
}
__device__ __forceinline__ void split2(float x, float y, uint32_t& hp, uint32_t& lp) {
    __nv_bfloat16 hx = __float2bfloat16(x), hy = __float2bfloat16(y);
    float lx = x - __bfloat162float(hx), ly = y - __bfloat162float(hy);
    hp = ((uint32_t)__bfloat16_as_ushort(hy) << 16) | __bfloat16_as_ushort(hx);
    __nv_bfloat16 lbx = __float2bfloat16(lx), lby = __float2bfloat16(ly);
    lp = ((uint32_t)__bfloat16_as_ushort(lby) << 16) | __bfloat16_as_ushort(lbx);
}

// ============================ prep: transpose + split weights ============================
template<int K>
__device__ __forceinline__ void split_tr(const float* __restrict__ W, __nv_bfloat16* H,
                                         __nv_bfloat16* L, int g, int gs) {
    for (int i = g; i < K * 128; i += gs) {
        int n = i / K, k = i - n * K;            // write-coalesced over k
        float v = W[(long)k * 128 + n];
        __nv_bfloat16 h = __float2bfloat16(v);
        float lo = v - __bfloat162float(h);
        H[(long)n * K + k] = h;
        L[(long)n * K + k] = __float2bfloat16(lo);
    }
}
__global__ void prep_weights(const float* W1, const float* W2, const float* W3,
                             const float* W11, const float* W12, const float* W13) {
    int g = blockIdx.x * blockDim.x + threadIdx.x;
    int gs = gridDim.x * blockDim.x;
    split_tr<384>(W1,  g_W1h,  g_W1l,  g, gs);
    split_tr<128>(W2,  g_W2h,  g_W2l,  g, gs);
    split_tr<128>(W3,  g_W3h,  g_W3l,  g, gs);
    split_tr<384>(W11, g_W11h, g_W11l, g, gs);
    split_tr<128>(W12, g_W12h, g_W12l, g, gs);
    split_tr<128>(W13, g_W13h, g_W13l, g, gs);
}

// ============================ shared building blocks ============================
// async B load: 128 rows x 128 bf16 (hi+lo)
__device__ __forceinline__ void asyncB(const __nv_bfloat16* __restrict__ Wh,
                                       const __nv_bfloat16* __restrict__ Wl,
                                       int Ktot, int kk, uint32_t bufAddr, int tid) {
    #pragma unroll
    for (int u = tid; u < 2048; u += NTHREADS) {
        int n = u >> 4, s = u & 15;
        uint32_t dst = bufAddr + n * (LDS_STRIDE * 2) + s * 16;
        CP_ASYNC16(dst, (const char*)(Wh + (long)n * Ktot + kk) + s * 16);
        CP_ASYNC16(dst + BLO_OFF, (const char*)(Wl + (long)n * Ktot + kk) + s * 16);
    }
    CP_COMMIT();
}

// build A hi/lo from 128 contiguous fp32 rows (row-major, stride NH)
__device__ __forceinline__ void buildA_rows(const float* __restrict__ srcbase,
                                            char* smA, int tid) {
    __nv_bfloat16* Ah = (__nv_bfloat16*)(smA + A_HI);
    __nv_bfloat16* Al = (__nv_bfloat16*)(smA + A_LO);
    #pragma unroll
    for (int u = tid; u < 128 * 32; u += NTHREADS) {
        int r = u >> 5, q = u & 31;
        float4 v = ((const float4*)(srcbase + (long)r * NH))[q];
        uint32_t h01, l01, h23, l23;
        split2(v.x, v.y, h01, l01);
        split2(v.z, v.w, h23, l23);
        *(uint2*)(Ah + r * LDS_STRIDE + q * 4) = make_uint2(h01, h23);
        *(uint2*)(Al + r * LDS_STRIDE + q * 4) = make_uint2(l01, l23);
    }
}

// one 128-K chunk of MMA: 8 k-steps, 3-combo hi/lo split. acc[8][4].
__device__ __forceinline__ void gemm_chunk(uint32_t sb, uint32_t bbase, int lane,
                                           int mbase, int nbase, float acc[8][4]) {
    const uint32_t aOff = (uint32_t)(((mbase + (lane & 15)) * LDS_STRIDE + ((lane >> 4) << 3)) * 2);
    const int bRow0 = nbase + ((lane >> 4) & 1) * 8 + (lane & 7);
    const int bCol  = ((lane >> 3) & 1) * 8;

    #pragma unroll
    for (int ks = 0; ks < 8; ks++) {
        const uint32_t k0b = ks * 32;
        uint32_t ah[4], al[4];
        ldsm_x4(ah, sb + A_HI + aOff + k0b);
        ldsm_x4(al, sb + A_LO + aOff + k0b);
        uint32_t bh[4][4], blr[4][4];
        #pragma unroll
        for (int p = 0; p < 4; p++) {
            uint32_t ba = (uint32_t)(((bRow0 + p * 16) * LDS_STRIDE + bCol) * 2) + k0b;
            ldsm_x4(bh[p],  bbase + ba);
            ldsm_x4(blr[p], bbase + BLO_OFF + ba);
        }
        #pragma unroll
        for (int nt = 0; nt < 8; nt++) {
            const uint32_t* fh = &bh[nt >> 1][(nt & 1) * 2];
            const uint32_t* fl = &blr[nt >> 1][(nt & 1) * 2];
            mma16816(acc[nt], ah, fh);
            mma16816(acc[nt], ah, fl);
            mma16816(acc[nt], al, fh);
        }
    }
}

__device__ __forceinline__ void zero_acc(float acc[8][4]) {
    #pragma unroll
    for (int nt = 0; nt < 8; nt++)
        #pragma unroll
        for (int j = 0; j < 4; j++) acc[nt][j] = 0.f;
}

// bias + gelu + hi/lo split back into A smem (warp tile 16 rows x 64 cols)
__device__ __forceinline__ void epi_gelu_to_A(float acc[8][4], const float* __restrict__ bias,
                                              char* smA, int lane, int mbase, int nbase) {
    __nv_bfloat16* Ah = (__nv_bfloat16*)(smA + A_HI);
    __nv_bfloat16* Al = (__nv_bfloat16*)(smA + A_LO);
    int g = lane >> 2, tig = lane & 3;
    #pragma unroll
    for (int nt = 0; nt < 8; nt++) {
        int col = nbase + nt * 8 + tig * 2;
        float2 b2 = *(const float2*)(bias + col);
        float x0 = gelu_f(acc[nt][0] + b2.x);
        float x1 = gelu_f(acc[nt][1] + b2.y);
        float x2 = gelu_f(acc[nt][2] + b2.x);
        float x3 = gelu_f(acc[nt][3] + b2.y);
        int row0 = mbase + g;
        uint32_t hp, lp;
        split2(x0, x1, hp, lp);
        *(uint32_t*)(Ah + row0 * LDS_STRIDE + col) = hp;
        *(uint32_t*)(Al + row0 * LDS_STRIDE + col) = lp;
        split2(x2, x3, hp, lp);
        *(uint32_t*)(Ah + (row0 + 8) * LDS_STRIDE + col) = hp;
        *(uint32_t*)(Al + (row0 + 8) * LDS_STRIDE + col) = lp;
    }
}

// ============================ precomp: Pa = src@W1a, Pc = src@W1c ============================
__device__ __forceinline__ void writeP(float acc[8][4], float* __restrict__ P,
                                       long base, int lane, int mbase, int nbase) {
    int g = lane >> 2, tig = lane & 3;
    #pragma unroll
    for (int nt = 0; nt < 8; nt++) {
        int col = nbase + nt * 8 + tig * 2;
        int row0 = mbase + g;
        *(float2*)(P + (base + row0) * NH + col)       = make_float2(acc[nt][0], acc[nt][1]);
        *(float2*)(P + (base + row0 + 8) * NH + col)   = make_float2(acc[nt][2], acc[nt][3]);
    }
}

__global__ __launch_bounds__(NTHREADS, 1)
void precomp_kernel(const float* __restrict__ src,
                    const __nv_bfloat16* __restrict__ Wh,
                    const __nv_bfloat16* __restrict__ Wl) {
    extern __shared__ char dsm[];
    char* smA = (char*)(((uintptr_t)dsm + 1023) & ~(uintptr_t)1023);
    const int tid = threadIdx.x, wid = tid >> 5, lane = tid & 31;
    const long base = (long)blockIdx.x * 128;
    const int mbase = (wid & 7) * 16;
    const int nbase = (wid >> 3) * 64;
    const uint32_t sb = smem_u32(smA);

    asyncB(Wh, Wl, 384, 0, sb + BUF0, tid);       // W1a
    buildA_rows(src + base * NH, smA, tid);
    CP_WAIT0();
    __syncthreads();
    asyncB(Wh, Wl, 384, 256, sb + BUF1, tid);     // W1c

    float acc[8][4];
    zero_acc(acc);
    gemm_chunk(sb, sb + BUF0, lane, mbase, nbase, acc);
    writeP(acc, g_Pa, base, lane, mbase, nbase);

    CP_WAIT0();
    __syncthreads();
    zero_acc(acc);
    gemm_chunk(sb, sb + BUF1, lane, mbase, nbase, acc);
    writeP(acc, g_Pc, base, lane, mbase, nbase);
}

// ============================ MMA stage ============================
template<bool EDGE>
__global__ __launch_bounds__(NTHREADS, 1)
void mma_stage(const float* __restrict__ hE,
               const int* __restrict__ Eidx,
               const float* __restrict__ maskA,
               const float* __restrict__ hVres,   // residual base for node stage (hV)
               const float* __restrict__ B1v, const float* __restrict__ B2v,
               const float* __restrict__ B3v,
               const float* __restrict__ lns, const float* __restrict__ lnb,
               float* __restrict__ outp) {
    extern __shared__ char dsm[];
    char* smA = (char*)(((uintptr_t)dsm + 1023) & ~(uintptr_t)1023);
    float* stage = (float*)(smA + BUF1);          // aliases BUF1 (last MMA uses BUF0)

    __shared__ int   gcent[128];
    __shared__ int   gnb[128];
    __shared__ float mkr[128];

    const int tid = threadIdx.x, wid = tid >> 5, lane = tid & 31;
    const long base = (long)blockIdx.x * 128;
    const int mbase = (wid & 7) * 16;
    const int nbase = (wid >> 3) * 64;
    const uint32_t sb = smem_u32(smA);

    const __nv_bfloat16* W1h = EDGE ? g_W11h : g_W1h;
    const __nv_bfloat16* W1l = EDGE ? g_W11l : g_W1l;
    const __nv_bfloat16* W2h = EDGE ? g_W12h : g_W2h;
    const __nv_bfloat16* W2l = EDGE ? g_W12l : g_W2l;
    const __nv_bfloat16* W3h = EDGE ? g_W13h : g_W3h;
    const __nv_bfloat16* W3l = EDGE ? g_W13l : g_W3l;

    asyncB(W1h, W1l, 384, 128, sb + BUF0, tid);   // W1b (edge chunk)
    buildA_rows(hE + base * NH, smA, tid);        // coalesced hE rows

    if (tid < 128) {
        long e = base + tid;
        int n = (int)(e / NK);
        gcent[tid] = n;
        gnb[tid] = (n >> 11) * NL + Eidx[e];
        if (!EDGE) mkr[tid] = maskA[e]; else mkr[tid] = 1.f;
    }
    CP_WAIT0();
    __syncthreads();

    asyncB(W2h, W2l, 128, 0, sb + BUF1, tid);     // prefetch W2

    float acc[8][4];
    zero_acc(acc);
    gemm_chunk(sb, sb + BUF0, lane, mbase, nbase, acc);
    __syncthreads();

    // ---------- epilogue L1: D + Pa[cent] + Pc[nbr] + b1 -> gelu -> A ----------
    {
        __nv_bfloat16* Ah = (__nv_bfloat16*)(smA + A_HI);
        __nv_bfloat16* Al = (__nv_bfloat16*)(smA + A_LO);
        int g = lane >> 2, tig = lane & 3;
        int r0 = mbase + g, r1 = r0 + 8;
        const float* pa0 = g_Pa + (long)gcent[r0] * NH;
        const float* pc0 = g_Pc + (long)gnb[r0] * NH;
        const float* pa1 = g_Pa + (long)gcent[r1] * NH;
        const float* pc1 = g_Pc + (long)gnb[r1] * NH;
        #pragma unroll
        for (int nt = 0; nt < 8; nt++) {
            int col = nbase + nt * 8 + tig * 2;
            float2 b2 = *(const float2*)(B1v + col);
            float2 a0 = *(const float2*)(pa0 + col);
            float2 c0 = *(const float2*)(pc0 + col);
            float2 a1 = *(const float2*)(pa1 + col);
            float2 c1 = *(const float2*)(pc1 + col);
            float x0 = gelu_f(acc[nt][0] + b2.x + a0.x + c0.x);
            float x1 = gelu_f(acc[nt][1] + b2.y + a0.y + c0.y);
            float x2 = gelu_f(acc[nt][2] + b2.x + a1.x + c1.x);
            float x3 = gelu_f(acc[nt][3] + b2.y + a1.y + c1.y);
            uint32_t hp, lp;
            split2(x0, x1, hp, lp);
            *(uint32_t*)(Ah + r0 * LDS_STRIDE + col) = hp;
            *(uint32_t*)(Al + r0 * LDS_STRIDE + col) = lp;
            split2(x2, x3, hp, lp);
            *(uint32_t*)(Ah + r1 * LDS_STRIDE + col) = hp;
            *(uint32_t*)(Al + r1 * LDS_STRIDE + col) = lp;
        }
    }
    CP_WAIT0();
    __syncthreads();

    // ---------- GEMM2 (BUF1), prefetch W3 -> BUF0 ----------
    asyncB(W3h, W3l, 128, 0, sb + BUF0, tid);
    zero_acc(acc);
    gemm_chunk(sb, sb + BUF1, lane, mbase, nbase, acc);
    __syncthreads();

    // ---------- epilogue L2 -> A ----------
    epi_gelu_to_A(acc, B2v, smA, lane, mbase, nbase);
    CP_WAIT0();
    __syncthreads();

    // ---------- GEMM3 (BUF0) ----------
    zero_acc(acc);
    gemm_chunk(sb, sb + BUF0, lane, mbase, nbase, acc);
    __syncthreads();   // BUF1 reads done -> stage may alias it

    // ---------- final epilogue: bias (+mask) -> fp32 stage ----------
    {
        int g = lane >> 2, tig = lane & 3;
        #pragma unroll
        for (int nt = 0; nt < 8; nt++) {
            int col = nbase + nt * 8 + tig * 2;
            float2 b2 = *(const float2*)(B3v + col);
            int row0 = mbase + g;
            float2 z0, z1;
            z0.x = (acc[nt][0] + b2.x) * mkr[row0];
            z0.y = (acc[nt][1] + b2.y) * mkr[row0];
            z1.x = (acc[nt][2] + b2.x) * mkr[row0 + 8];
            z1.y = (acc[nt][3] + b2.y) * mkr[row0 + 8];
            *(float2*)(stage + row0 * STG_STRIDE + col) = z0;
            *(float2*)(stage + (row0 + 8) * STG_STRIDE + col) = z1;
        }
    }
    __syncthreads();

    if (!EDGE) {
        int c = tid & 127, quarter = tid >> 7;
        int n0 = (int)(base / NK), n1 = (int)((base + 127) / NK);
        for (int n = n0 + quarter; n <= n1; n += 4) {
            int r0 = n * NK - (int)base; if (r0 < 0) r0 = 0;
            int r1 = n * NK + NK - (int)base; if (r1 > 128) r1 = 128;
            float sacc = 0.f;
            for (int r = r0; r < r1; r++) sacc += stage[r * STG_STRIDE + c];
            int slot = (((n * NK) >> 7) == (int)blockIdx.x) ? 0 : 1;
            g_psum[(long)slot * BL * NH + (long)n * NH + c] = sacc;
        }
        (void)hVres;
    } else {
        float4 sV = ((const float4*)lns)[lane];
        float4 bV = ((const float4*)lnb)[lane];
        #pragma unroll
        for (int i = 0; i < 8; i++) {
            int r = wid * 8 + i;
            long ge = base + r;
            float4 m = ((const float4*)(stage + r * STG_STRIDE))[lane];
            float4 e4 = ((const float4*)(hE + ge * NH))[lane];
            float4 v;
            v.x = e4.x + m.x; v.y = e4.y + m.y; v.z = e4.z + m.z; v.w = e4.w + m.w;
            float mu = warp_sum(v.x + v.y + v.z + v.w) * (1.0f / NH);
            float dx = v.x - mu, dy = v.y - mu, dz = v.z - mu, dw = v.w - mu;
            float var = warp_sum(dx * dx + dy * dy + dz * dz + dw * dw) * (1.0f / NH);
            float inv = rsqrtf(var + LNEPS);
            float4 o;
            o.x = dx * inv * sV.x + bV.x; o.y = dy * inv * sV.y + bV.y;
            o.z = dz * inv * sV.z + bV.z; o.w = dw * inv * sV.w + bV.w;
            ((float4*)(outp + ge * NH))[lane] = o;
        }
    }
}

// ============================ node reduce + LN1 ============================
__global__ void node_reduce(const float* __restrict__ hV, const float* __restrict__ lns,
                            const float* __restrict__ lnb) {
    __shared__ float red[8];
    int n = blockIdx.x, c = threadIdx.x;
    float p = g_psum[(long)n * NH + c];
    if (((n * NK) >> 7) != ((n * NK + NK - 1) >> 7))
        p += g_psum[(long)BL * NH + (long)n * NH + c];
    float h = hV[(long)n * NH + c] + p * SCALE_INV;
    float s = warp_sum(h);
    if ((c & 31) == 0) red[c >> 5] = s;
    __syncthreads();
    float mu = (red[0] + red[1] + red[2] + red[3]) * (1.0f / NH);
    float d = h - mu;
    float q = warp_sum(d * d);
    if ((c & 31) == 0) red[4 + (c >> 5)] = q;
    __syncthreads();
    float var = (red[4] + red[5] + red[6] + red[7]) * (1.0f / NH);
    g_hV1[(long)n * NH + c] = d * rsqrtf(var + LNEPS) * lns[c] + lnb[c];
}

// ============================ FFN (fp32, verified) ============================
__global__ __launch_bounds__(256, 1)
void ffn_kernel(const float* __restrict__ maskV,
                const float* __restrict__ Wi, const float* __restrict__ bi,
                const float* __restrict__ Wo, const float* __restrict__ bo,
                const float* __restrict__ lns, const float* __restrict__ lnb,
                float* __restrict__ out) {
    extern __shared__ float sm[];
    float* Xr = sm;            // [16][128]
    float* Hd = Xr + 16*NH;    // [16][512]
    float* Wc = Hd + 16*512;   // weight staging

    const float* hV1 = g_hV1;
    const int tid = threadIdx.x;
    const long row0 = (long)blockIdx.x * 16;

    for (int t = tid; t < 16*32; t += 256) {
        int r = t >> 5, c = t & 31;
        ((float4*)(Xr + r*NH))[c] = ((const float4*)(hV1 + (row0+r)*NH))[c];
    }
    __syncthreads();

    {
        int cg = tid & 63, rg = tid >> 6;
        float acc[4][8];
        #pragma unroll
        for (int i = 0; i < 4; i++)
            #pragma unroll
            for (int j = 0; j < 8; j++) acc[i][j] = 0.f;
        for (int kk = 0; kk < NH; kk += 16) {
            for (int u = tid; u < 16*128; u += 256) {
                int wr = u >> 7, wc = u & 127;
                ((float4*)(Wc + wr*512))[wc] = ((const float4*)(Wi + (long)(kk+wr)*512))[wc];
            }
            __syncthreads();
            #pragma unroll
            for (int k = 0; k < 16; k++) {
                float4 w0 = ((const float4*)(Wc + k*512))[cg*2];
                float4 w1 = ((const float4*)(Wc + k*512))[cg*2+1];
                #pragma unroll
                for (int i = 0; i < 4; i++) {
                    float x = Xr[(rg*4+i)*NH + kk + k];
                    acc[i][0]+=x*w0.x; acc[i][1]+=x*w0.y; acc[i][2]+=x*w0.z; acc[i][3]+=x*w0.w;
                    acc[i][4]+=x*w1.x; acc[i][5]+=x*w1.y; acc[i][6]+=x*w1.z; acc[i][7]+=x*w1.w;
                }
            }
            __syncthreads();
        }
        float4 b0 = ((const float4*)bi)[cg*2];
        float4 b1 = ((const float4*)bi)[cg*2+1];
        #pragma unroll
        for (int i = 0; i < 4; i++) {
            int r = rg*4 + i;
            float4 o0, o1;
            o0.x = gelu_f(acc[i][0]+b0.x); o0.y = gelu_f(acc[i][1]+b0.y);
            o0.z = gelu_f(acc[i][2]+b0.z); o0.w = gelu_f(acc[i][3]+b0.w);
            o1.x = gelu_f(acc[i][4]+b1.x); o1.y = gelu_f(acc[i][5]+b1.y);
            o1.z = gelu_f(acc[i][6]+b1.z); o1.w = gelu_f(acc[i][7]+b1.w);
            ((float4*)(Hd + r*512))[cg*2]   = o0;
            ((float4*)(Hd + r*512))[cg*2+1] = o1;
        }
    }
    __syncthreads();

    {
        int cg = tid & 63, rg = tid >> 6;
        float acc[4][2];
        #pragma unroll
        for (int i = 0; i < 4; i++) { acc[i][0]=0.f; acc[i][1]=0.f; }
        for (int kk = 0; kk < 512; kk += 32) {
            for (int u = tid; u < 32*32; u += 256) {
                int wr = u >> 5, wc = u & 31;
                ((float4*)(Wc + wr*NH))[wc] = ((const float4*)(Wo + (long)(kk+wr)*NH))[wc];
            }
            __syncthreads();
            #pragma unroll
            for (int k = 0; k < 32; k++) {
                float2 w = ((const float2*)(Wc + k*NH))[cg];
                #pragma unroll
                for (int i = 0; i < 4; i++) {
                    float x = Hd[(rg*4+i)*512 + kk + k];
                    acc[i][0] += x*w.x; acc[i][1] += x*w.y;
                }
            }
            __syncthreads();
        }
        float2 bv = ((const float2*)bo)[cg];
        #pragma unroll
        for (int i = 0; i < 4; i++) {
            int r = rg*4 + i;
            float2 z;
            z.x = acc[i][0] + bv.x + Xr[r*NH + cg*2];
            z.y = acc[i][1] + bv.y + Xr[r*NH + cg*2 + 1];
            ((float2*)(Hd + r*NH))[cg] = z;
        }
    }
    __syncthreads();

    {
        int wid = tid >> 5, lane = tid & 31;
        float4 sV = ((const float4*)lns)[lane];
        float4 bV = ((const float4*)lnb)[lane];
        #pragma unroll
        for (int rr = 0; rr < 2; rr++) {
            int r = wid*2 + rr;
            long grow = row0 + r;
            float mk = maskV[grow];
            float4 v = ((const float4*)(Hd + r*NH))[lane];
            float mu = warp_sum(v.x+v.y+v.z+v.w) * (1.0f/NH);
            float dx=v.x-mu, dy=v.y-mu, dz=v.z-mu, dw=v.w-mu;
            float var = warp_sum(dx*dx+dy*dy+dz*dz+dw*dw) * (1.0f/NH);
            float inv = rsqrtf(var + LNEPS);
            float4 o;
            o.x = (dx*inv*sV.x + bV.x)*mk; o.y = (dy*inv*sV.y + bV.y)*mk;
            o.z = (dz*inv*sV.z + bV.z)*mk; o.w = (dw*inv*sV.w + bV.w)*mk;
            ((float4*)(out + grow*NH))[lane] = o;
        }
    }
}

// ============================ host ============================
extern "C" void kernel_launch(void* const* d_in, const int* in_sizes, int n_in,
                              void* d_out, int out_size) {
    (void)in_sizes; (void)n_in; (void)out_size;
    const float* hV    = (const float*)d_in[0];
    const float* hE    = (const float*)d_in[1];
    const int*   Eidx  = (const int*)d_in[2];
    const float* maskV = (const float*)d_in[3];
    const float* maskA = (const float*)d_in[4];
    const float *W1 =(const float*)d_in[5],  *b1 =(const float*)d_in[6];
    const float *W2 =(const float*)d_in[7],  *b2 =(const float*)d_in[8];
    const float *W3 =(const float*)d_in[9],  *b3 =(const float*)d_in[10];
    const float *W11=(const float*)d_in[11], *b11=(const float*)d_in[12];
    const float *W12=(const float*)d_in[13], *b12=(const float*)d_in[14];
    const float *W13=(const float*)d_in[15], *b13=(const float*)d_in[16];
    const float *Wi =(const float*)d_in[17], *bi =(const float*)d_in[18];
    const float *Wo =(const float*)d_in[19], *bo =(const float*)d_in[20];
    const float *ln1s=(const float*)d_in[21], *ln1b=(const float*)d_in[22];
    const float *ln2s=(const float*)d_in[23], *ln2b=(const float*)d_in[24];
    const float *ln3s=(const float*)d_in[25], *ln3b=(const float*)d_in[26];

    float* outV = (float*)d_out;
    float* outE = outV + (long)BL*NH;

    cudaFuncSetAttribute(mma_stage<false>, cudaFuncAttributeMaxDynamicSharedMemorySize, DSMEM_TOTAL);
    cudaFuncSetAttribute(mma_stage<true>,  cudaFuncAttributeMaxDynamicSharedMemorySize, DSMEM_TOTAL);
    cudaFuncSetAttribute(precomp_kernel,   cudaFuncAttributeMaxDynamicSharedMemorySize, DSMEM_TOTAL);
    const int sm2 = (16*NH + 16*512 + 16*512) * (int)sizeof(float);
    cudaFuncSetAttribute(ffn_kernel, cudaFuncAttributeMaxDynamicSharedMemorySize, sm2);

    __nv_bfloat16 *w1h, *w1l, *w11h, *w11l;
    cudaGetSymbolAddress((void**)&w1h,  g_W1h);
    cudaGetSymbolAddress((void**)&w1l,  g_W1l);
    cudaGetSymbolAddress((void**)&w11h, g_W11h);
    cudaGetSymbolAddress((void**)&w11l, g_W11l);

    prep_weights<<<148, 256>>>(W1, W2, W3, W11, W12, W13);
    precomp_kernel<<<BL/128, NTHREADS, DSMEM_TOTAL>>>(hV, w1h, w1l);
    mma_stage<false><<<NTILE, NTHREADS, DSMEM_TOTAL>>>(hE, Eidx, maskA, hV,
                                                       b1, b2, b3, nullptr, nullptr, nullptr);
    node_reduce<<<BL, 128>>>(hV, ln1s, ln1b);
    ffn_kernel<<<BL/16, 256, sm2>>>(maskV, Wi, bi, Wo, bo, ln2s, ln2b, outV);
    precomp_kernel<<<BL/128, NTHREADS, DSMEM_TOTAL>>>(outV, w11h, w11l);
    mma_stage<true><<<NTILE, NTHREADS, DSMEM_TOTAL>>>(hE, Eidx, maskA, nullptr,
                                                      b11, b12, b13, ln3s, ln3b, outE);
}

// round 9
// speedup vs baseline: 5.0130x; 1.1507x over previous
#include <cuda_runtime.h>
#include <cuda_fp16.h>
#include <math.h>
#include <stdint.h>

#define NB 2
#define NL 2048
#define NK 48
#define NH 128
#define BL (NB*NL)              // 4096
#define NEDGE (BL*NK)           // 196608
#define NTILE (NEDGE/128)       // 1536
#define SCALE_INV (1.0f/30.0f)
#define LNEPS 1e-5f

#define NTHREADS 512

// padded smem row stride (fp16 elements): 136*2 = 272B -> conflict-free ldmatrix
#define LDS_STRIDE 136
#define A_HI 0                        // A fp16 [128][136]
#define BUF0 34816                    // B buffer 0 (hi at +0, lo at +34816)
#define BUF1 104448                   // B buffer 1
#define BLO_OFF 34816
#define SM_BYTES 174080
#define DSMEM_TOTAL (SM_BYTES + 1024)
#define STG_STRIDE 132                // fp32 stage aliases BUF1 (67.6KB <= 69.6KB)

// ---- transposed + hi/lo split fp16 weights (K-major [N=128][Ktot]) ----
__device__ __align__(16) __half g_W1h[128*384],  g_W1l[128*384];
__device__ __align__(16) __half g_W2h[128*128],  g_W2l[128*128];
__device__ __align__(16) __half g_W3h[128*128],  g_W3l[128*128];
__device__ __align__(16) __half g_W11h[128*384], g_W11l[128*384];
__device__ __align__(16) __half g_W12h[128*128], g_W12l[128*128];
__device__ __align__(16) __half g_W13h[128*128], g_W13l[128*128];
__device__ float g_psum[2L*BL*NH];       // 2 slots per node
__device__ float g_hV1[(long)BL*NH];
__device__ float g_Pa[(long)BL*NH];      // node precomp: hV @ W1a
__device__ float g_Pc[(long)BL*NH];      // node precomp: hV @ W1c

// ============================ helpers ============================
__device__ __forceinline__ uint32_t smem_u32(const void* p) {
    uint32_t a;
    asm("{ .reg .u64 t; cvta.to.shared.u64 t, %1; cvt.u32.u64 %0, t; }" : "=r"(a) : "l"(p));
    return a;
}
__device__ __forceinline__ void ldsm_x4(uint32_t* r, uint32_t addr) {
    asm volatile("ldmatrix.sync.aligned.m8n8.x4.shared.b16 {%0,%1,%2,%3}, [%4];"
        : "=r"(r[0]), "=r"(r[1]), "=r"(r[2]), "=r"(r[3]) : "r"(addr));
}
__device__ __forceinline__ void mma16816(float* d, const uint32_t* a, const uint32_t* b) {
    asm volatile("mma.sync.aligned.m16n8k16.row.col.f32.f16.f16.f32 "
        "{%0,%1,%2,%3}, {%4,%5,%6,%7}, {%8,%9}, {%0,%1,%2,%3};"
        : "+f"(d[0]), "+f"(d[1]), "+f"(d[2]), "+f"(d[3])
        : "r"(a[0]), "r"(a[1]), "r"(a[2]), "r"(a[3]), "r"(b[0]), "r"(b[1]));
}
#define CP_ASYNC16(dst, src) \
    asm volatile("cp.async.cg.shared.global [%0], [%1], 16;" :: "r"(dst), "l"(src))
#define CP_COMMIT() asm volatile("cp.async.commit_group;" ::: "memory")
#define CP_WAIT0()  asm volatile("cp.async.wait_group 0;" ::: "memory")

__device__ __forceinline__ float gelu_f(float x) {
    return 0.5f * x * (1.0f + erff(x * 0.70710678118654752f));
}
__device__ __forceinline__ float warp_sum(float v) {
    #pragma unroll
    for (int o = 16; o > 0; o >>= 1) v += __shfl_xor_sync(0xffffffffu, v, o);
    return v;
}
__device__ __forceinline__ uint32_t pack_h2(float x, float y) {
    __half2 h = __floats2half2_rn(x, y);
    return *(uint32_t*)&h;
}

// ============================ prep: transpose + split weights ============================
template<int K>
__device__ __forceinline__ void split_tr(const float* __restrict__ W, __half* H,
                                         __half* L, int g, int gs) {
    for (int i = g; i < K * 128; i += gs) {
        int n = i / K, k = i - n * K;            // write-coalesced over k
        float v = W[(long)k * 128 + n];
        __half h = __float2half_rn(v);
        float lo = v - __half2float(h);
        H[(long)n * K + k] = h;
        L[(long)n * K + k] = __float2half_rn(lo);
    }
}
__global__ void prep_weights(const float* W1, const float* W2, const float* W3,
                             const float* W11, const float* W12, const float* W13) {
    int g = blockIdx.x * blockDim.x + threadIdx.x;
    int gs = gridDim.x * blockDim.x;
    split_tr<384>(W1,  g_W1h,  g_W1l,  g, gs);
    split_tr<128>(W2,  g_W2h,  g_W2l,  g, gs);
    split_tr<128>(W3,  g_W3h,  g_W3l,  g, gs);
    split_tr<384>(W11, g_W11h, g_W11l, g, gs);
    split_tr<128>(W12, g_W12h, g_W12l, g, gs);
    split_tr<128>(W13, g_W13h, g_W13l, g, gs);
}

// ============================ shared building blocks ============================
// async B load: 128 rows x 128 fp16 (hi+lo)
__device__ __forceinline__ void asyncB(const __half* __restrict__ Wh,
                                       const __half* __restrict__ Wl,
                                       int Ktot, int kk, uint32_t bufAddr, int tid) {
    #pragma unroll
    for (int u = tid; u < 2048; u += NTHREADS) {
        int n = u >> 4, s = u & 15;
        uint32_t dst = bufAddr + n * (LDS_STRIDE * 2) + s * 16;
        CP_ASYNC16(dst, (const char*)(Wh + (long)n * Ktot + kk) + s * 16);
        CP_ASYNC16(dst + BLO_OFF, (const char*)(Wl + (long)n * Ktot + kk) + s * 16);
    }
    CP_COMMIT();
}

// build A fp16 from 128 contiguous fp32 rows (row-major, stride NH)
__device__ __forceinline__ void buildA_rows(const float* __restrict__ srcbase,
                                            char* smA, int tid) {
    __half* Ah = (__half*)(smA + A_HI);
    #pragma unroll
    for (int u = tid; u < 128 * 32; u += NTHREADS) {
        int r = u >> 5, q = u & 31;
        float4 v = ((const float4*)(srcbase + (long)r * NH))[q];
        *(uint2*)(Ah + r * LDS_STRIDE + q * 4) =
            make_uint2(pack_h2(v.x, v.y), pack_h2(v.z, v.w));
    }
}

// one 128-K chunk of MMA: 8 k-steps, 2-combo fp16 weight split. acc[8][4].
__device__ __forceinline__ void gemm_chunk(uint32_t sb, uint32_t bbase, int lane,
                                           int mbase, int nbase, float acc[8][4]) {
    const uint32_t aOff = (uint32_t)(((mbase + (lane & 15)) * LDS_STRIDE + ((lane >> 4) << 3)) * 2);
    const int bRow0 = nbase + ((lane >> 4) & 1) * 8 + (lane & 7);
    const int bCol  = ((lane >> 3) & 1) * 8;

    #pragma unroll
    for (int ks = 0; ks < 8; ks++) {
        const uint32_t k0b = ks * 32;
        uint32_t ah[4];
        ldsm_x4(ah, sb + A_HI + aOff + k0b);
        uint32_t bh[4][4], blr[4][4];
        #pragma unroll
        for (int p = 0; p < 4; p++) {
            uint32_t ba = (uint32_t)(((bRow0 + p * 16) * LDS_STRIDE + bCol) * 2) + k0b;
            ldsm_x4(bh[p],  bbase + ba);
            ldsm_x4(blr[p], bbase + BLO_OFF + ba);
        }
        #pragma unroll
        for (int nt = 0; nt < 8; nt++) {
            const uint32_t* fh = &bh[nt >> 1][(nt & 1) * 2];
            const uint32_t* fl = &blr[nt >> 1][(nt & 1) * 2];
            mma16816(acc[nt], ah, fh);
            mma16816(acc[nt], ah, fl);
        }
    }
}

__device__ __forceinline__ void zero_acc(float acc[8][4]) {
    #pragma unroll
    for (int nt = 0; nt < 8; nt++)
        #pragma unroll
        for (int j = 0; j < 4; j++) acc[nt][j] = 0.f;
}

// bias + gelu -> fp16 A smem (warp tile 16 rows x 64 cols)
__device__ __forceinline__ void epi_gelu_to_A(float acc[8][4], const float* __restrict__ bias,
                                              char* smA, int lane, int mbase, int nbase) {
    __half* Ah = (__half*)(smA + A_HI);
    int g = lane >> 2, tig = lane & 3;
    #pragma unroll
    for (int nt = 0; nt < 8; nt++) {
        int col = nbase + nt * 8 + tig * 2;
        float2 b2 = *(const float2*)(bias + col);
        float x0 = gelu_f(acc[nt][0] + b2.x);
        float x1 = gelu_f(acc[nt][1] + b2.y);
        float x2 = gelu_f(acc[nt][2] + b2.x);
        float x3 = gelu_f(acc[nt][3] + b2.y);
        int row0 = mbase + g;
        *(uint32_t*)(Ah + row0 * LDS_STRIDE + col) = pack_h2(x0, x1);
        *(uint32_t*)(Ah + (row0 + 8) * LDS_STRIDE + col) = pack_h2(x2, x3);
    }
}

// ============================ precomp: Pa = src@W1a, Pc = src@W1c ============================
__device__ __forceinline__ void writeP(float acc[8][4], float* __restrict__ P,
                                       long base, int lane, int mbase, int nbase) {
    int g = lane >> 2, tig = lane & 3;
    #pragma unroll
    for (int nt = 0; nt < 8; nt++) {
        int col = nbase + nt * 8 + tig * 2;
        int row0 = mbase + g;
        *(float2*)(P + (base + row0) * NH + col)       = make_float2(acc[nt][0], acc[nt][1]);
        *(float2*)(P + (base + row0 + 8) * NH + col)   = make_float2(acc[nt][2], acc[nt][3]);
    }
}

__global__ __launch_bounds__(NTHREADS, 1)
void precomp_kernel(const float* __restrict__ src,
                    const __half* __restrict__ Wh,
                    const __half* __restrict__ Wl) {
    extern __shared__ char dsm[];
    char* smA = (char*)(((uintptr_t)dsm + 1023) & ~(uintptr_t)1023);
    const int tid = threadIdx.x, wid = tid >> 5, lane = tid & 31;
    const long base = (long)blockIdx.x * 128;
    const int mbase = (wid & 7) * 16;
    const int nbase = (wid >> 3) * 64;
    const uint32_t sb = smem_u32(smA);

    asyncB(Wh, Wl, 384, 0, sb + BUF0, tid);       // W1a
    buildA_rows(src + base * NH, smA, tid);
    CP_WAIT0();
    __syncthreads();
    asyncB(Wh, Wl, 384, 256, sb + BUF1, tid);     // W1c

    float acc[8][4];
    zero_acc(acc);
    gemm_chunk(sb, sb + BUF0, lane, mbase, nbase, acc);
    writeP(acc, g_Pa, base, lane, mbase, nbase);

    CP_WAIT0();
    __syncthreads();
    zero_acc(acc);
    gemm_chunk(sb, sb + BUF1, lane, mbase, nbase, acc);
    writeP(acc, g_Pc, base, lane, mbase, nbase);
}

// ============================ MMA stage ============================
template<bool EDGE>
__global__ __launch_bounds__(NTHREADS, 1)
void mma_stage(const float* __restrict__ hE,
               const int* __restrict__ Eidx,
               const float* __restrict__ maskA,
               const float* __restrict__ B1v, const float* __restrict__ B2v,
               const float* __restrict__ B3v,
               const float* __restrict__ lns, const float* __restrict__ lnb,
               float* __restrict__ outp) {
    extern __shared__ char dsm[];
    char* smA = (char*)(((uintptr_t)dsm + 1023) & ~(uintptr_t)1023);
    float* stage = (float*)(smA + BUF1);          // aliases BUF1 (last MMA uses BUF0)

    __shared__ int   gcent[128];
    __shared__ int   gnb[128];
    __shared__ float mkr[128];

    const int tid = threadIdx.x, wid = tid >> 5, lane = tid & 31;
    const long base = (long)blockIdx.x * 128;
    const int mbase = (wid & 7) * 16;
    const int nbase = (wid >> 3) * 64;
    const uint32_t sb = smem_u32(smA);

    const __half* W1h = EDGE ? g_W11h : g_W1h;
    const __half* W1l = EDGE ? g_W11l : g_W1l;
    const __half* W2h = EDGE ? g_W12h : g_W2h;
    const __half* W2l = EDGE ? g_W12l : g_W2l;
    const __half* W3h = EDGE ? g_W13h : g_W3h;
    const __half* W3l = EDGE ? g_W13l : g_W3l;

    asyncB(W1h, W1l, 384, 128, sb + BUF0, tid);   // W1b (edge chunk)
    buildA_rows(hE + base * NH, smA, tid);        // coalesced hE rows

    if (tid < 128) {
        long e = base + tid;
        int n = (int)(e / NK);
        gcent[tid] = n;
        gnb[tid] = (n >> 11) * NL + Eidx[e];
        if (!EDGE) mkr[tid] = maskA[e]; else mkr[tid] = 1.f;
    }
    CP_WAIT0();
    __syncthreads();

    asyncB(W2h, W2l, 128, 0, sb + BUF1, tid);     // prefetch W2

    float acc[8][4];
    zero_acc(acc);
    gemm_chunk(sb, sb + BUF0, lane, mbase, nbase, acc);
    __syncthreads();

    // ---------- epilogue L1: D + Pa[cent] + Pc[nbr] + b1 -> gelu -> A ----------
    {
        __half* Ah = (__half*)(smA + A_HI);
        int g = lane >> 2, tig = lane & 3;
        int r0 = mbase + g, r1 = r0 + 8;
        const float* pa0 = g_Pa + (long)gcent[r0] * NH;
        const float* pc0 = g_Pc + (long)gnb[r0] * NH;
        const float* pa1 = g_Pa + (long)gcent[r1] * NH;
        const float* pc1 = g_Pc + (long)gnb[r1] * NH;
        #pragma unroll
        for (int nt = 0; nt < 8; nt++) {
            int col = nbase + nt * 8 + tig * 2;
            float2 b2 = *(const float2*)(B1v + col);
            float2 a0 = *(const float2*)(pa0 + col);
            float2 c0 = *(const float2*)(pc0 + col);
            float2 a1 = *(const float2*)(pa1 + col);
            float2 c1 = *(const float2*)(pc1 + col);
            float x0 = gelu_f(acc[nt][0] + b2.x + a0.x + c0.x);
            float x1 = gelu_f(acc[nt][1] + b2.y + a0.y + c0.y);
            float x2 = gelu_f(acc[nt][2] + b2.x + a1.x + c1.x);
            float x3 = gelu_f(acc[nt][3] + b2.y + a1.y + c1.y);
            *(uint32_t*)(Ah + r0 * LDS_STRIDE + col) = pack_h2(x0, x1);
            *(uint32_t*)(Ah + r1 * LDS_STRIDE + col) = pack_h2(x2, x3);
        }
    }
    CP_WAIT0();
    __syncthreads();

    // ---------- GEMM2 (BUF1), prefetch W3 -> BUF0 ----------
    asyncB(W3h, W3l, 128, 0, sb + BUF0, tid);
    zero_acc(acc);
    gemm_chunk(sb, sb + BUF1, lane, mbase, nbase, acc);
    __syncthreads();

    // ---------- epilogue L2 -> A ----------
    epi_gelu_to_A(acc, B2v, smA, lane, mbase, nbase);
    CP_WAIT0();
    __syncthreads();

    // ---------- GEMM3 (BUF0) ----------
    zero_acc(acc);
    gemm_chunk(sb, sb + BUF0, lane, mbase, nbase, acc);
    __syncthreads();   // BUF1 reads done -> stage may alias it

    // ---------- final epilogue: bias (+mask) -> fp32 stage ----------
    {
        int g = lane >> 2, tig = lane & 3;
        #pragma unroll
        for (int nt = 0; nt < 8; nt++) {
            int col = nbase + nt * 8 + tig * 2;
            float2 b2 = *(const float2*)(B3v + col);
            int row0 = mbase + g;
            float2 z0, z1;
            z0.x = (acc[nt][0] + b2.x) * mkr[row0];
            z0.y = (acc[nt][1] + b2.y) * mkr[row0];
            z1.x = (acc[nt][2] + b2.x) * mkr[row0 + 8];
            z1.y = (acc[nt][3] + b2.y) * mkr[row0 + 8];
            *(float2*)(stage + row0 * STG_STRIDE + col) = z0;
            *(float2*)(stage + (row0 + 8) * STG_STRIDE + col) = z1;
        }
    }
    __syncthreads();

    if (!EDGE) {
        int c = tid & 127, quarter = tid >> 7;
        int n0 = (int)(base / NK), n1 = (int)((base + 127) / NK);
        for (int n = n0 + quarter; n <= n1; n += 4) {
            int r0 = n * NK - (int)base; if (r0 < 0) r0 = 0;
            int r1 = n * NK + NK - (int)base; if (r1 > 128) r1 = 128;
            float sacc = 0.f;
            for (int r = r0; r < r1; r++) sacc += stage[r * STG_STRIDE + c];
            int slot = (((n * NK) >> 7) == (int)blockIdx.x) ? 0 : 1;
            g_psum[(long)slot * BL * NH + (long)n * NH + c] = sacc;
        }
    } else {
        float4 sV = ((const float4*)lns)[lane];
        float4 bV = ((const float4*)lnb)[lane];
        #pragma unroll
        for (int i = 0; i < 8; i++) {
            int r = wid * 8 + i;
            long ge = base + r;
            float4 m = ((const float4*)(stage + r * STG_STRIDE))[lane];
            float4 e4 = ((const float4*)(hE + ge * NH))[lane];
            float4 v;
            v.x = e4.x + m.x; v.y = e4.y + m.y; v.z = e4.z + m.z; v.w = e4.w + m.w;
            float mu = warp_sum(v.x + v.y + v.z + v.w) * (1.0f / NH);
            float dx = v.x - mu, dy = v.y - mu, dz = v.z - mu, dw = v.w - mu;
            float var = warp_sum(dx * dx + dy * dy + dz * dz + dw * dw) * (1.0f / NH);
            float inv = rsqrtf(var + LNEPS);
            float4 o;
            o.x = dx * inv * sV.x + bV.x; o.y = dy * inv * sV.y + bV.y;
            o.z = dz * inv * sV.z + bV.z; o.w = dw * inv * sV.w + bV.w;
            ((float4*)(outp + ge * NH))[lane] = o;
        }
    }
}

// ============================ node reduce + LN1 ============================
__global__ void node_reduce(const float* __restrict__ hV, const float* __restrict__ lns,
                            const float* __restrict__ lnb) {
    __shared__ float red[8];
    int n = blockIdx.x, c = threadIdx.x;
    float p = g_psum[(long)n * NH + c];
    if (((n * NK) >> 7) != ((n * NK + NK - 1) >> 7))
        p += g_psum[(long)BL * NH + (long)n * NH + c];
    float h = hV[(long)n * NH + c] + p * SCALE_INV;
    float s = warp_sum(h);
    if ((c & 31) == 0) red[c >> 5] = s;
    __syncthreads();
    float mu = (red[0] + red[1] + red[2] + red[3]) * (1.0f / NH);
    float d = h - mu;
    float q = warp_sum(d * d);
    if ((c & 31) == 0) red[4 + (c >> 5)] = q;
    __syncthreads();
    float var = (red[4] + red[5] + red[6] + red[7]) * (1.0f / NH);
    g_hV1[(long)n * NH + c] = d * rsqrtf(var + LNEPS) * lns[c] + lnb[c];
}

// ============================ FFN (fp32, verified) ============================
__global__ __launch_bounds__(256, 1)
void ffn_kernel(const float* __restrict__ maskV,
                const float* __restrict__ Wi, const float* __restrict__ bi,
                const float* __restrict__ Wo, const float* __restrict__ bo,
                const float* __restrict__ lns, const float* __restrict__ lnb,
                float* __restrict__ out) {
    extern __shared__ float sm[];
    float* Xr = sm;            // [16][128]
    float* Hd = Xr + 16*NH;    // [16][512]
    float* Wc = Hd + 16*512;   // weight staging

    const float* hV1 = g_hV1;
    const int tid = threadIdx.x;
    const long row0 = (long)blockIdx.x * 16;

    for (int t = tid; t < 16*32; t += 256) {
        int r = t >> 5, c = t & 31;
        ((float4*)(Xr + r*NH))[c] = ((const float4*)(hV1 + (row0+r)*NH))[c];
    }
    __syncthreads();

    {
        int cg = tid & 63, rg = tid >> 6;
        float acc[4][8];
        #pragma unroll
        for (int i = 0; i < 4; i++)
            #pragma unroll
            for (int j = 0; j < 8; j++) acc[i][j] = 0.f;
        for (int kk = 0; kk < NH; kk += 16) {
            for (int u = tid; u < 16*128; u += 256) {
                int wr = u >> 7, wc = u & 127;
                ((float4*)(Wc + wr*512))[wc] = ((const float4*)(Wi + (long)(kk+wr)*512))[wc];
            }
            __syncthreads();
            #pragma unroll
            for (int k = 0; k < 16; k++) {
                float4 w0 = ((const float4*)(Wc + k*512))[cg*2];
                float4 w1 = ((const float4*)(Wc + k*512))[cg*2+1];
                #pragma unroll
                for (int i = 0; i < 4; i++) {
                    float x = Xr[(rg*4+i)*NH + kk + k];
                    acc[i][0]+=x*w0.x; acc[i][1]+=x*w0.y; acc[i][2]+=x*w0.z; acc[i][3]+=x*w0.w;
                    acc[i][4]+=x*w1.x; acc[i][5]+=x*w1.y; acc[i][6]+=x*w1.z; acc[i][7]+=x*w1.w;
                }
            }
            __syncthreads();
        }
        float4 b0 = ((const float4*)bi)[cg*2];
        float4 b1 = ((const float4*)bi)[cg*2+1];
        #pragma unroll
        for (int i = 0; i < 4; i++) {
            int r = rg*4 + i;
            float4 o0, o1;
            o0.x = gelu_f(acc[i][0]+b0.x); o0.y = gelu_f(acc[i][1]+b0.y);
            o0.z = gelu_f(acc[i][2]+b0.z); o0.w = gelu_f(acc[i][3]+b0.w);
            o1.x = gelu_f(acc[i][4]+b1.x); o1.y = gelu_f(acc[i][5]+b1.y);
            o1.z = gelu_f(acc[i][6]+b1.z); o1.w = gelu_f(acc[i][7]+b1.w);
            ((float4*)(Hd + r*512))[cg*2]   = o0;
            ((float4*)(Hd + r*512))[cg*2+1] = o1;
        }
    }
    __syncthreads();

    {
        int cg = tid & 63, rg = tid >> 6;
        float acc[4][2];
        #pragma unroll
        for (int i = 0; i < 4; i++) { acc[i][0]=0.f; acc[i][1]=0.f; }
        for (int kk = 0; kk < 512; kk += 32) {
            for (int u = tid; u < 32*32; u += 256) {
                int wr = u >> 5, wc = u & 31;
                ((float4*)(Wc + wr*NH))[wc] = ((const float4*)(Wo + (long)(kk+wr)*NH))[wc];
            }
            __syncthreads();
            #pragma unroll
            for (int k = 0; k < 32; k++) {
                float2 w = ((const float2*)(Wc + k*NH))[cg];
                #pragma unroll
                for (int i = 0; i < 4; i++) {
                    float x = Hd[(rg*4+i)*512 + kk + k];
                    acc[i][0] += x*w.x; acc[i][1] += x*w.y;
                }
            }
            __syncthreads();
        }
        float2 bv = ((const float2*)bo)[cg];
        #pragma unroll
        for (int i = 0; i < 4; i++) {
            int r = rg*4 + i;
            float2 z;
            z.x = acc[i][0] + bv.x + Xr[r*NH + cg*2];
            z.y = acc[i][1] + bv.y + Xr[r*NH + cg*2 + 1];
            ((float2*)(Hd + r*NH))[cg] = z;
        }
    }
    __syncthreads();

    {
        int wid = tid >> 5, lane = tid & 31;
        float4 sV = ((const float4*)lns)[lane];
        float4 bV = ((const float4*)lnb)[lane];
        #pragma unroll
        for (int rr = 0; rr < 2; rr++) {
            int r = wid*2 + rr;
            long grow = row0 + r;
            float mk = maskV[grow];
            float4 v = ((const float4*)(Hd + r*NH))[lane];
            float mu = warp_sum(v.x+v.y+v.z+v.w) * (1.0f/NH);
            float dx=v.x-mu, dy=v.y-mu, dz=v.z-mu, dw=v.w-mu;
            float var = warp_sum(dx*dx+dy*dy+dz*dz+dw*dw) * (1.0f/NH);
            float inv = rsqrtf(var + LNEPS);
            float4 o;
            o.x = (dx*inv*sV.x + bV.x)*mk; o.y = (dy*inv*sV.y + bV.y)*mk;
            o.z = (dz*inv*sV.z + bV.z)*mk; o.w = (dw*inv*sV.w + bV.w)*mk;
            ((float4*)(out + grow*NH))[lane] = o;
        }
    }
}

// ============================ host ============================
extern "C" void kernel_launch(void* const* d_in, const int* in_sizes, int n_in,
                              void* d_out, int out_size) {
    (void)in_sizes; (void)n_in; (void)out_size;
    const float* hV    = (const float*)d_in[0];
    const float* hE    = (const float*)d_in[1];
    const int*   Eidx  = (const int*)d_in[2];
    const float* maskV = (const float*)d_in[3];
    const float* maskA = (const float*)d_in[4];
    const float *W1 =(const float*)d_in[5],  *b1 =(const float*)d_in[6];
    const float *W2 =(const float*)d_in[7],  *b2 =(const float*)d_in[8];
    const float *W3 =(const float*)d_in[9],  *b3 =(const float*)d_in[10];
    const float *W11=(const float*)d_in[11], *b11=(const float*)d_in[12];
    const float *W12=(const float*)d_in[13], *b12=(const float*)d_in[14];
    const float *W13=(const float*)d_in[15], *b13=(const float*)d_in[16];
    const float *Wi =(const float*)d_in[17], *bi =(const float*)d_in[18];
    const float *Wo =(const float*)d_in[19], *bo =(const float*)d_in[20];
    const float *ln1s=(const float*)d_in[21], *ln1b=(const float*)d_in[22];
    const float *ln2s=(const float*)d_in[23], *ln2b=(const float*)d_in[24];
    const float *ln3s=(const float*)d_in[25], *ln3b=(const float*)d_in[26];

    float* outV = (float*)d_out;
    float* outE = outV + (long)BL*NH;

    cudaFuncSetAttribute(mma_stage<false>, cudaFuncAttributeMaxDynamicSharedMemorySize, DSMEM_TOTAL);
    cudaFuncSetAttribute(mma_stage<true>,  cudaFuncAttributeMaxDynamicSharedMemorySize, DSMEM_TOTAL);
    cudaFuncSetAttribute(precomp_kernel,   cudaFuncAttributeMaxDynamicSharedMemorySize, DSMEM_TOTAL);
    const int sm2 = (16*NH + 16*512 + 16*512) * (int)sizeof(float);
    cudaFuncSetAttribute(ffn_kernel, cudaFuncAttributeMaxDynamicSharedMemorySize, sm2);

    __half *w1h, *w1l, *w11h, *w11l;
    cudaGetSymbolAddress((void**)&w1h,  g_W1h);
    cudaGetSymbolAddress((void**)&w1l,  g_W1l);
    cudaGetSymbolAddress((void**)&w11h, g_W11h);
    cudaGetSymbolAddress((void**)&w11l, g_W11l);

    prep_weights<<<148, 256>>>(W1, W2, W3, W11, W12, W13);
    precomp_kernel<<<BL/128, NTHREADS, DSMEM_TOTAL>>>(hV, w1h, w1l);
    mma_stage<false><<<NTILE, NTHREADS, DSMEM_TOTAL>>>(hE, Eidx, maskA,
                                                       b1, b2, b3, nullptr, nullptr, nullptr);
    node_reduce<<<BL, 128>>>(hV, ln1s, ln1b);
    ffn_kernel<<<BL/16, 256, sm2>>>(maskV, Wi, bi, Wo, bo, ln2s, ln2b, outV);
    precomp_kernel<<<BL/128, NTHREADS, DSMEM_TOTAL>>>(outV, w11h, w11l);
    mma_stage<true><<<NTILE, NTHREADS, DSMEM_TOTAL>>>(hE, Eidx, maskA,
                                                      b11, b12, b13, ln3s, ln3b, outE);
}

// round 14
// speedup vs baseline: 6.4669x; 1.2900x over previous
#include <cuda_runtime.h>
#include <cuda_fp16.h>
#include <math.h>
#include <stdint.h>

#define NB 2
#define NL 2048
#define NK 48
#define NH 128
#define BL (NB*NL)              // 4096
#define NEDGE (BL*NK)           // 196608
#define NTILE (NEDGE/128)       // 1536
#define SCALE_INV (1.0f/30.0f)
#define LNEPS 1e-5f

// fp16 smem row stride: 136 elems = 272B -> conflict-free ldmatrix
#define LDS_STRIDE 136
#define B_HILO_OFF 34816              // 128*136*2 : lo plane offset inside a B buffer
#define B_BYTES 69632                 // hi+lo

// ---- mma_stage smem: A[128x136] + single B ----
#define MS_A 0
#define MS_B 34816
#define MS_SMEM (104448 + 1024)
#define STG_STRIDE 132                // fp32 stage aliases B (67584 <= 69632)

// ---- precomp smem: A[64x136] + single B ----
#define PC_A 0
#define PC_B 17408
#define PC_SMEM (87040 + 1024)

// ---- ffn smem ----
#define FF_A1 0                       // 32x136 fp16 = 8704
#define FF_A2 8704                    // 32x520 fp16 = 33280
#define FF_B0 41984
#define FF_B1 111616
#define FF_STG 181248                 // 32x132 fp32 = 16896
#define FF_SMEM (198144 + 1024)
#define A2_STRIDE 520

// ---- transposed + hi/lo split fp16 weights (K-major [N][Ktot]) ----
__device__ __align__(16) __half g_W1h[128*384],  g_W1l[128*384];
__device__ __align__(16) __half g_W2h[128*128],  g_W2l[128*128];
__device__ __align__(16) __half g_W3h[128*128],  g_W3l[128*128];
__device__ __align__(16) __half g_W11h[128*384], g_W11l[128*384];
__device__ __align__(16) __half g_W12h[128*128], g_W12l[128*128];
__device__ __align__(16) __half g_W13h[128*128], g_W13l[128*128];
__device__ __align__(16) __half g_Wih[512*128],  g_Wil[512*128];   // Wi: K=128,N=512
__device__ __align__(16) __half g_Woh[128*512],  g_Wol[128*512];   // Wo: K=512,N=128
__device__ float g_psum[2L*BL*NH];
__device__ float g_hV1[(long)BL*NH];
__device__ float g_Pa[(long)BL*NH];
__device__ float g_Pc[(long)BL*NH];

// ============================ helpers ============================
__device__ __forceinline__ uint32_t smem_u32(const void* p) {
    uint32_t a;
    asm("{ .reg .u64 t; cvta.to.shared.u64 t, %1; cvt.u32.u64 %0, t; }" : "=r"(a) : "l"(p));
    return a;
}
__device__ __forceinline__ void ldsm_x4(uint32_t* r, uint32_t addr) {
    asm volatile("ldmatrix.sync.aligned.m8n8.x4.shared.b16 {%0,%1,%2,%3}, [%4];"
        : "=r"(r[0]), "=r"(r[1]), "=r"(r[2]), "=r"(r[3]) : "r"(addr));
}
__device__ __forceinline__ void mma16816(float* d, const uint32_t* a, const uint32_t* b) {
    asm volatile("mma.sync.aligned.m16n8k16.row.col.f32.f16.f16.f32 "
        "{%0,%1,%2,%3}, {%4,%5,%6,%7}, {%8,%9}, {%0,%1,%2,%3};"
        : "+f"(d[0]), "+f"(d[1]), "+f"(d[2]), "+f"(d[3])
        : "r"(a[0]), "r"(a[1]), "r"(a[2]), "r"(a[3]), "r"(b[0]), "r"(b[1]));
}
#define CP_ASYNC16(dst, src) \
    asm volatile("cp.async.cg.shared.global [%0], [%1], 16;" :: "r"(dst), "l"(src))
#define CP_COMMIT() asm volatile("cp.async.commit_group;" ::: "memory")
#define CP_WAIT0()  asm volatile("cp.async.wait_group 0;" ::: "memory")

__device__ __forceinline__ float gelu_f(float x) {
    return 0.5f * x * (1.0f + erff(x * 0.70710678118654752f));
}
__device__ __forceinline__ float warp_sum(float v) {
    #pragma unroll
    for (int o = 16; o > 0; o >>= 1) v += __shfl_xor_sync(0xffffffffu, v, o);
    return v;
}
__device__ __forceinline__ uint32_t pack_h2(float x, float y) {
    __half2 h = __floats2half2_rn(x, y);
    return *(uint32_t*)&h;
}

// ============================ prep: transpose + split weights ============================
template<int K, int N>
__device__ __forceinline__ void split_tr(const float* __restrict__ W, __half* H,
                                         __half* L, int g, int gs) {
    for (int i = g; i < K * N; i += gs) {
        int n = i / K, k = i - n * K;
        float v = W[(long)k * N + n];
        __half h = __float2half_rn(v);
        float lo = v - __half2float(h);
        H[(long)n * K + k] = h;
        L[(long)n * K + k] = __float2half_rn(lo);
    }
}
__global__ void prep_weights(const float* W1, const float* W2, const float* W3,
                             const float* W11, const float* W12, const float* W13,
                             const float* Wi, const float* Wo) {
    int g = blockIdx.x * blockDim.x + threadIdx.x;
    int gs = gridDim.x * blockDim.x;
    split_tr<384,128>(W1,  g_W1h,  g_W1l,  g, gs);
    split_tr<128,128>(W2,  g_W2h,  g_W2l,  g, gs);
    split_tr<128,128>(W3,  g_W3h,  g_W3l,  g, gs);
    split_tr<384,128>(W11, g_W11h, g_W11l, g, gs);
    split_tr<128,128>(W12, g_W12h, g_W12l, g, gs);
    split_tr<128,128>(W13, g_W13h, g_W13l, g, gs);
    split_tr<128,512>(Wi,  g_Wih,  g_Wil,  g, gs);
    split_tr<512,128>(Wo,  g_Woh,  g_Wol,  g, gs);
}

// ============================ building blocks ============================
// async B load: 128 rows x 128 fp16 (hi+lo) into buf (hi) / buf+B_HILO_OFF (lo)
__device__ __forceinline__ void asyncB(const __half* __restrict__ Wh,
                                       const __half* __restrict__ Wl,
                                       int Ktot, int kk, uint32_t bufAddr, int tid) {
    #pragma unroll
    for (int u = tid; u < 2048; u += 256) {
        int n = u >> 4, s = u & 15;
        uint32_t dst = bufAddr + n * (LDS_STRIDE * 2) + s * 16;
        CP_ASYNC16(dst, (const char*)(Wh + (long)n * Ktot + kk) + s * 16);
        CP_ASYNC16(dst + B_HILO_OFF, (const char*)(Wl + (long)n * Ktot + kk) + s * 16);
    }
    CP_COMMIT();
}

// build A fp16 from R contiguous fp32 rows (stride NH)
template<int R>
__device__ __forceinline__ void buildA_rows(const float* __restrict__ srcbase,
                                            __half* Ah, int tid) {
    #pragma unroll
    for (int u = tid; u < R * 32; u += 256) {
        int r = u >> 5, q = u & 31;
        float4 v = ((const float4*)(srcbase + (long)r * NH))[q];
        *(uint2*)(Ah + r * LDS_STRIDE + q * 4) =
            make_uint2(pack_h2(v.x, v.y), pack_h2(v.z, v.w));
    }
}

// generic 128-K chunk: warp tile (MT*16) rows x (NT*8) cols, 2-combo fp16 split
// aBase: smem addr of A element (row mbase+(lane&15), col (lane>>4)*8); aStride bytes/row
template<int MT, int NT>
__device__ __forceinline__ void gemm_g(uint32_t aBase, int aStride, uint32_t bbase,
                                       int lane, int nbase, float acc[MT][NT][4]) {
    const int bRow0 = nbase + ((lane >> 4) & 1) * 8 + (lane & 7);
    const int bCol  = ((lane >> 3) & 1) * 8;
    #pragma unroll
    for (int ks = 0; ks < 8; ks++) {
        const uint32_t k0b = ks * 32;
        uint32_t ah[MT][4];
        #pragma unroll
        for (int mt = 0; mt < MT; mt++)
            ldsm_x4(ah[mt], aBase + mt * 16 * aStride + k0b);
        uint32_t bh[NT/2][4], bl[NT/2][4];
        #pragma unroll
        for (int p = 0; p < NT/2; p++) {
            uint32_t ba = (uint32_t)(((bRow0 + p * 16) * LDS_STRIDE + bCol) * 2) + k0b;
            ldsm_x4(bh[p], bbase + ba);
            ldsm_x4(bl[p], bbase + B_HILO_OFF + ba);
        }
        #pragma unroll
        for (int mt = 0; mt < MT; mt++)
            #pragma unroll
            for (int nt = 0; nt < NT; nt++) {
                const uint32_t* fh = &bh[nt >> 1][(nt & 1) * 2];
                const uint32_t* fl = &bl[nt >> 1][(nt & 1) * 2];
                mma16816(acc[mt][nt], ah[mt], fh);
                mma16816(acc[mt][nt], ah[mt], fl);
            }
    }
}
template<int MT, int NT>
__device__ __forceinline__ void zero_g(float acc[MT][NT][4]) {
    #pragma unroll
    for (int mt = 0; mt < MT; mt++)
        #pragma unroll
        for (int nt = 0; nt < NT; nt++)
            #pragma unroll
            for (int j = 0; j < 4; j++) acc[mt][nt][j] = 0.f;
}

// ============================ precomp: Pa = src@W1a, Pc = src@W1c ============================
// 64 rows/CTA, 8 warps, warp tile 16x64 (MT=1, NT=8)
__global__ __launch_bounds__(256, 2)
void precomp_kernel(const float* __restrict__ src,
                    const __half* __restrict__ Wh,
                    const __half* __restrict__ Wl) {
    extern __shared__ char dsm[];
    char* smA = (char*)(((uintptr_t)dsm + 1023) & ~(uintptr_t)1023);
    const int tid = threadIdx.x, wid = tid >> 5, lane = tid & 31;
    const long base = (long)blockIdx.x * 64;
    const int mbase = (wid & 3) * 16;
    const int nbase = (wid >> 2) * 64;
    const uint32_t sb = smem_u32(smA);
    const uint32_t aBase = sb + PC_A + (uint32_t)(((mbase + (lane & 15)) * LDS_STRIDE + ((lane >> 4) << 3)) * 2);
    const int g = lane >> 2, tig = lane & 3;

    asyncB(Wh, Wl, 384, 0, sb + PC_B, tid);           // W1a
    buildA_rows<64>(src + base * NH, (__half*)(smA + PC_A), tid);
    CP_WAIT0();
    __syncthreads();

    float acc[1][8][4];
    zero_g<1,8>(acc);
    gemm_g<1,8>(aBase, LDS_STRIDE*2, sb + PC_B, lane, nbase, acc);
    __syncthreads();                                  // all reads of B done
    asyncB(Wh, Wl, 384, 256, sb + PC_B, tid);         // W1c (overlaps writeP)
    #pragma unroll
    for (int nt = 0; nt < 8; nt++) {
        int col = nbase + nt * 8 + tig * 2;
        *(float2*)(g_Pa + (base + mbase + g) * NH + col)     = make_float2(acc[0][nt][0], acc[0][nt][1]);
        *(float2*)(g_Pa + (base + mbase + g + 8) * NH + col) = make_float2(acc[0][nt][2], acc[0][nt][3]);
    }
    CP_WAIT0();
    __syncthreads();
    zero_g<1,8>(acc);
    gemm_g<1,8>(aBase, LDS_STRIDE*2, sb + PC_B, lane, nbase, acc);
    #pragma unroll
    for (int nt = 0; nt < 8; nt++) {
        int col = nbase + nt * 8 + tig * 2;
        *(float2*)(g_Pc + (base + mbase + g) * NH + col)     = make_float2(acc[0][nt][0], acc[0][nt][1]);
        *(float2*)(g_Pc + (base + mbase + g + 8) * NH + col) = make_float2(acc[0][nt][2], acc[0][nt][3]);
    }
}

// ============================ MMA stage: 128 rows, 8 warps, warp tile 32x64 ============================
template<bool EDGE>
__global__ __launch_bounds__(256, 2)
void mma_stage(const float* __restrict__ hE,
               const int* __restrict__ Eidx,
               const float* __restrict__ maskA,
               const float* __restrict__ B1v, const float* __restrict__ B2v,
               const float* __restrict__ B3v,
               const float* __restrict__ lns, const float* __restrict__ lnb,
               float* __restrict__ outp) {
    extern __shared__ char dsm[];
    char* smA = (char*)(((uintptr_t)dsm + 1023) & ~(uintptr_t)1023);
    __half* Ah = (__half*)(smA + MS_A);
    float* stage = (float*)(smA + MS_B);              // aliases B after final sync

    __shared__ int   gcent[128];
    __shared__ int   gnb[128];
    __shared__ float mkr[128];

    const int tid = threadIdx.x, wid = tid >> 5, lane = tid & 31;
    const long base = (long)blockIdx.x * 128;
    const int mbase = (wid & 3) * 32;
    const int nbase = (wid >> 2) * 64;
    const uint32_t sb = smem_u32(smA);
    const uint32_t aBase = sb + MS_A + (uint32_t)(((mbase + (lane & 15)) * LDS_STRIDE + ((lane >> 4) << 3)) * 2);
    const uint32_t bb = sb + MS_B;
    const int g = lane >> 2, tig = lane & 3;

    const __half* W1h = EDGE ? g_W11h : g_W1h;
    const __half* W1l = EDGE ? g_W11l : g_W1l;
    const __half* W2h = EDGE ? g_W12h : g_W2h;
    const __half* W2l = EDGE ? g_W12l : g_W2l;
    const __half* W3h = EDGE ? g_W13h : g_W3h;
    const __half* W3l = EDGE ? g_W13l : g_W3l;

    asyncB(W1h, W1l, 384, 128, bb, tid);              // W1b (edge chunk)
    buildA_rows<128>(hE + base * NH, Ah, tid);

    if (tid < 128) {
        long e = base + tid;
        int n = (int)(e / NK);
        gcent[tid] = n;
        gnb[tid] = (n >> 11) * NL + Eidx[e];
        if (!EDGE) mkr[tid] = maskA[e]; else mkr[tid] = 1.f;
    }
    CP_WAIT0();
    __syncthreads();

    float acc[2][8][4];
    zero_g<2,8>(acc);
    gemm_g<2,8>(aBase, LDS_STRIDE*2, bb, lane, nbase, acc);
    __syncthreads();                                  // B reads complete
    asyncB(W2h, W2l, 128, 0, bb, tid);                // overlaps epilogue 1

    // ---------- epilogue L1: D + Pa[cent] + Pc[nbr] + b1 -> gelu -> A ----------
    #pragma unroll
    for (int mt = 0; mt < 2; mt++) {
        int r0 = mbase + mt * 16 + g, r1 = r0 + 8;
        const float* pa0 = g_Pa + (long)gcent[r0] * NH;
        const float* pc0 = g_Pc + (long)gnb[r0] * NH;
        const float* pa1 = g_Pa + (long)gcent[r1] * NH;
        const float* pc1 = g_Pc + (long)gnb[r1] * NH;
        #pragma unroll
        for (int nt = 0; nt < 8; nt++) {
            int col = nbase + nt * 8 + tig * 2;
            float2 b2 = *(const float2*)(B1v + col);
            float2 a0 = *(const float2*)(pa0 + col);
            float2 c0 = *(const float2*)(pc0 + col);
            float2 a1 = *(const float2*)(pa1 + col);
            float2 c1 = *(const float2*)(pc1 + col);
            float x0 = gelu_f(acc[mt][nt][0] + b2.x + a0.x + c0.x);
            float x1 = gelu_f(acc[mt][nt][1] + b2.y + a0.y + c0.y);
            float x2 = gelu_f(acc[mt][nt][2] + b2.x + a1.x + c1.x);
            float x3 = gelu_f(acc[mt][nt][3] + b2.y + a1.y + c1.y);
            *(uint32_t*)(Ah + r0 * LDS_STRIDE + col) = pack_h2(x0, x1);
            *(uint32_t*)(Ah + r1 * LDS_STRIDE + col) = pack_h2(x2, x3);
        }
    }
    CP_WAIT0();
    __syncthreads();

    // ---------- GEMM2 ----------
    zero_g<2,8>(acc);
    gemm_g<2,8>(aBase, LDS_STRIDE*2, bb, lane, nbase, acc);
    __syncthreads();
    asyncB(W3h, W3l, 128, 0, bb, tid);                // overlaps epilogue 2

    // ---------- epilogue L2: gelu(D+b2) -> A ----------
    #pragma unroll
    for (int mt = 0; mt < 2; mt++) {
        int r0 = mbase + mt * 16 + g, r1 = r0 + 8;
        #pragma unroll
        for (int nt = 0; nt < 8; nt++) {
            int col = nbase + nt * 8 + tig * 2;
            float2 b2 = *(const float2*)(B2v + col);
            float x0 = gelu_f(acc[mt][nt][0] + b2.x);
            float x1 = gelu_f(acc[mt][nt][1] + b2.y);
            float x2 = gelu_f(acc[mt][nt][2] + b2.x);
            float x3 = gelu_f(acc[mt][nt][3] + b2.y);
            *(uint32_t*)(Ah + r0 * LDS_STRIDE + col) = pack_h2(x0, x1);
            *(uint32_t*)(Ah + r1 * LDS_STRIDE + col) = pack_h2(x2, x3);
        }
    }
    CP_WAIT0();
    __syncthreads();

    // ---------- GEMM3 ----------
    zero_g<2,8>(acc);
    gemm_g<2,8>(aBase, LDS_STRIDE*2, bb, lane, nbase, acc);
    __syncthreads();                                  // B reads done -> stage may alias

    // ---------- final epilogue: bias (+mask) -> fp32 stage ----------
    #pragma unroll
    for (int mt = 0; mt < 2; mt++) {
        int r0 = mbase + mt * 16 + g;
        #pragma unroll
        for (int nt = 0; nt < 8; nt++) {
            int col = nbase + nt * 8 + tig * 2;
            float2 b2 = *(const float2*)(B3v + col);
            float2 z0, z1;
            z0.x = (acc[mt][nt][0] + b2.x) * mkr[r0];
            z0.y = (acc[mt][nt][1] + b2.y) * mkr[r0];
            z1.x = (acc[mt][nt][2] + b2.x) * mkr[r0 + 8];
            z1.y = (acc[mt][nt][3] + b2.y) * mkr[r0 + 8];
            *(float2*)(stage + r0 * STG_STRIDE + col) = z0;
            *(float2*)(stage + (r0 + 8) * STG_STRIDE + col) = z1;
        }
    }
    __syncthreads();

    if (!EDGE) {
        int c = tid & 127, half = tid >> 7;
        int n0 = (int)(base / NK), n1 = (int)((base + 127) / NK);
        for (int n = n0 + half; n <= n1; n += 2) {
            int r0 = n * NK - (int)base; if (r0 < 0) r0 = 0;
            int r1 = n * NK + NK - (int)base; if (r1 > 128) r1 = 128;
            float sacc = 0.f;
            for (int r = r0; r < r1; r++) sacc += stage[r * STG_STRIDE + c];
            int slot = (((n * NK) >> 7) == (int)blockIdx.x) ? 0 : 1;
            g_psum[(long)slot * BL * NH + (long)n * NH + c] = sacc;
        }
    } else {
        float4 sV = ((const float4*)lns)[lane];
        float4 bV = ((const float4*)lnb)[lane];
        #pragma unroll
        for (int i = 0; i < 16; i++) {
            int r = wid * 16 + i;
            long ge = base + r;
            float4 m = ((const float4*)(stage + r * STG_STRIDE))[lane];
            float4 e4 = ((const float4*)(hE + ge * NH))[lane];
            float4 v;
            v.x = e4.x + m.x; v.y = e4.y + m.y; v.z = e4.z + m.z; v.w = e4.w + m.w;
            float mu = warp_sum(v.x + v.y + v.z + v.w) * (1.0f / NH);
            float dx = v.x - mu, dy = v.y - mu, dz = v.z - mu, dw = v.w - mu;
            float var = warp_sum(dx * dx + dy * dy + dz * dz + dw * dw) * (1.0f / NH);
            float inv = rsqrtf(var + LNEPS);
            float4 o;
            o.x = dx * inv * sV.x + bV.x; o.y = dy * inv * sV.y + bV.y;
            o.z = dz * inv * sV.z + bV.z; o.w = dw * inv * sV.w + bV.w;
            ((float4*)(outp + ge * NH))[lane] = o;
        }
    }
}

// ============================ node reduce + LN1 ============================
__global__ void node_reduce(const float* __restrict__ hV, const float* __restrict__ lns,
                            const float* __restrict__ lnb) {
    __shared__ float red[8];
    int n = blockIdx.x, c = threadIdx.x;
    float p = g_psum[(long)n * NH + c];
    if (((n * NK) >> 7) != ((n * NK + NK - 1) >> 7))
        p += g_psum[(long)BL * NH + (long)n * NH + c];
    float h = hV[(long)n * NH + c] + p * SCALE_INV;
    float s = warp_sum(h);
    if ((c & 31) == 0) red[c >> 5] = s;
    __syncthreads();
    float mu = (red[0] + red[1] + red[2] + red[3]) * (1.0f / NH);
    float d = h - mu;
    float q = warp_sum(d * d);
    if ((c & 31) == 0) red[4 + (c >> 5)] = q;
    __syncthreads();
    float var = (red[4] + red[5] + red[6] + red[7]) * (1.0f / NH);
    g_hV1[(long)n * NH + c] = d * rsqrtf(var + LNEPS) * lns[c] + lnb[c];
}

// ============================ FFN: fp16 MMA, 32 rows/CTA ============================
__global__ __launch_bounds__(256, 1)
void ffn_mma(const float* __restrict__ maskV,
             const float* __restrict__ bi, const float* __restrict__ bo,
             const float* __restrict__ lns, const float* __restrict__ lnb,
             float* __restrict__ out) {
    extern __shared__ char dsm[];
    char* smA = (char*)(((uintptr_t)dsm + 1023) & ~(uintptr_t)1023);
    __half* A1 = (__half*)(smA + FF_A1);
    __half* A2 = (__half*)(smA + FF_A2);
    float* stage = (float*)(smA + FF_STG);

    const int tid = threadIdx.x, wid = tid >> 5, lane = tid & 31;
    const long rbase = (long)blockIdx.x * 32;
    const int mbase = (wid & 1) * 16;
    const int nbase = (wid >> 1) * 32;
    const uint32_t sb = smem_u32(smA);
    const int g = lane >> 2, tig = lane & 3;
    const uint32_t aBase1 = sb + FF_A1 + (uint32_t)(((mbase + (lane & 15)) * LDS_STRIDE + ((lane >> 4) << 3)) * 2);

    asyncB(g_Wih, g_Wil, 128, 0, sb + FF_B0, tid);    // Wi chunk 0
    buildA_rows<32>(g_hV1 + rbase * NH, A1, tid);
    CP_WAIT0();
    __syncthreads();

    // ---------- layer 1: 4 N-chunks of 128 ----------
    float acc[1][4][4];
    #pragma unroll 1
    for (int j = 0; j < 4; j++) {
        uint32_t cur = (j & 1) ? (sb + FF_B1) : (sb + FF_B0);
        uint32_t nxt = (j & 1) ? (sb + FF_B0) : (sb + FF_B1);
        if (j < 3) asyncB(g_Wih + (long)(j + 1) * 128 * 128, g_Wil + (long)(j + 1) * 128 * 128,
                          128, 0, nxt, tid);
        else       asyncB(g_Woh, g_Wol, 512, 0, nxt, tid);
        zero_g<1,4>(acc);
        gemm_g<1,4>(aBase1, LDS_STRIDE*2, cur, lane, nbase, acc);
        // gelu + bias -> A2 slice j
        #pragma unroll
        for (int nt = 0; nt < 4; nt++) {
            int col = nbase + nt * 8 + tig * 2;
            float2 b2 = *(const float2*)(bi + j * 128 + col);
            float x0 = gelu_f(acc[0][nt][0] + b2.x);
            float x1 = gelu_f(acc[0][nt][1] + b2.y);
            float x2 = gelu_f(acc[0][nt][2] + b2.x);
            float x3 = gelu_f(acc[0][nt][3] + b2.y);
            *(uint32_t*)(A2 + (mbase + g) * A2_STRIDE + j * 128 + col)     = pack_h2(x0, x1);
            *(uint32_t*)(A2 + (mbase + g + 8) * A2_STRIDE + j * 128 + col) = pack_h2(x2, x3);
        }
        CP_WAIT0();
        __syncthreads();
    }

    // ---------- layer 2: 4 K-chunks accumulate ----------
    float acc2[1][4][4];
    zero_g<1,4>(acc2);
    #pragma unroll 1
    for (int c = 0; c < 4; c++) {
        int ch = 4 + c;
        uint32_t cur = (ch & 1) ? (sb + FF_B1) : (sb + FF_B0);
        uint32_t nxt = (ch & 1) ? (sb + FF_B0) : (sb + FF_B1);
        if (c < 3) asyncB(g_Woh, g_Wol, 512, (c + 1) * 128, nxt, tid);
        uint32_t aBase2 = sb + FF_A2 +
            (uint32_t)(((mbase + (lane & 15)) * A2_STRIDE + ((lane >> 4) << 3) + c * 128) * 2);
        gemm_g<1,4>(aBase2, A2_STRIDE*2, cur, lane, nbase, acc2);
        CP_WAIT0();
        __syncthreads();
    }

    // ---------- final: + bo + residual -> stage ----------
    #pragma unroll
    for (int nt = 0; nt < 4; nt++) {
        int col = nbase + nt * 8 + tig * 2;
        float2 b2 = *(const float2*)(bo + col);
        float2 r0 = *(const float2*)(g_hV1 + (rbase + mbase + g) * NH + col);
        float2 r1 = *(const float2*)(g_hV1 + (rbase + mbase + g + 8) * NH + col);
        float2 z0, z1;
        z0.x = acc2[0][nt][0] + b2.x + r0.x;
        z0.y = acc2[0][nt][1] + b2.y + r0.y;
        z1.x = acc2[0][nt][2] + b2.x + r1.x;
        z1.y = acc2[0][nt][3] + b2.y + r1.y;
        *(float2*)(stage + (mbase + g) * STG_STRIDE + col) = z0;
        *(float2*)(stage + (mbase + g + 8) * STG_STRIDE + col) = z1;
    }
    __syncthreads();

    // ---------- per-row LN2 + mask_V -> out ----------
    {
        float4 sV = ((const float4*)lns)[lane];
        float4 bV = ((const float4*)lnb)[lane];
        #pragma unroll
        for (int rr = 0; rr < 4; rr++) {
            int r = wid * 4 + rr;
            long grow = rbase + r;
            float mk = maskV[grow];
            float4 v = ((const float4*)(stage + r * STG_STRIDE))[lane];
            float mu = warp_sum(v.x + v.y + v.z + v.w) * (1.0f / NH);
            float dx = v.x - mu, dy = v.y - mu, dz = v.z - mu, dw = v.w - mu;
            float var = warp_sum(dx * dx + dy * dy + dz * dz + dw * dw) * (1.0f / NH);
            float inv = rsqrtf(var + LNEPS);
            float4 o;
            o.x = (dx * inv * sV.x + bV.x) * mk; o.y = (dy * inv * sV.y + bV.y) * mk;
            o.z = (dz * inv * sV.z + bV.z) * mk; o.w = (dw * inv * sV.w + bV.w) * mk;
            ((float4*)(out + grow * NH))[lane] = o;
        }
    }
}

// ============================ host ============================
extern "C" void kernel_launch(void* const* d_in, const int* in_sizes, int n_in,
                              void* d_out, int out_size) {
    (void)in_sizes; (void)n_in; (void)out_size;
    const float* hV    = (const float*)d_in[0];
    const float* hE    = (const float*)d_in[1];
    const int*   Eidx  = (const int*)d_in[2];
    const float* maskV = (const float*)d_in[3];
    const float* maskA = (const float*)d_in[4];
    const float *W1 =(const float*)d_in[5],  *b1 =(const float*)d_in[6];
    const float *W2 =(const float*)d_in[7],  *b2 =(const float*)d_in[8];
    const float *W3 =(const float*)d_in[9],  *b3 =(const float*)d_in[10];
    const float *W11=(const float*)d_in[11], *b11=(const float*)d_in[12];
    const float *W12=(const float*)d_in[13], *b12=(const float*)d_in[14];
    const float *W13=(const float*)d_in[15], *b13=(const float*)d_in[16];
    const float *Wi =(const float*)d_in[17], *bi =(const float*)d_in[18];
    const float *Wo =(const float*)d_in[19], *bo =(const float*)d_in[20];
    const float *ln1s=(const float*)d_in[21], *ln1b=(const float*)d_in[22];
    const float *ln2s=(const float*)d_in[23], *ln2b=(const float*)d_in[24];
    const float *ln3s=(const float*)d_in[25], *ln3b=(const float*)d_in[26];

    float* outV = (float*)d_out;
    float* outE = outV + (long)BL*NH;

    cudaFuncSetAttribute(mma_stage<false>, cudaFuncAttributeMaxDynamicSharedMemorySize, MS_SMEM);
    cudaFuncSetAttribute(mma_stage<true>,  cudaFuncAttributeMaxDynamicSharedMemorySize, MS_SMEM);
    cudaFuncSetAttribute(precomp_kernel,   cudaFuncAttributeMaxDynamicSharedMemorySize, PC_SMEM);
    cudaFuncSetAttribute(ffn_mma,          cudaFuncAttributeMaxDynamicSharedMemorySize, FF_SMEM);

    __half *w1h, *w1l, *w11h, *w11l;
    cudaGetSymbolAddress((void**)&w1h,  g_W1h);
    cudaGetSymbolAddress((void**)&w1l,  g_W1l);
    cudaGetSymbolAddress((void**)&w11h, g_W11h);
    cudaGetSymbolAddress((void**)&w11l, g_W11l);

    prep_weights<<<148, 256>>>(W1, W2, W3, W11, W12, W13, Wi, Wo);
    precomp_kernel<<<BL/64, 256, PC_SMEM>>>(hV, w1h, w1l);
    mma_stage<false><<<NTILE, 256, MS_SMEM>>>(hE, Eidx, maskA,
                                              b1, b2, b3, nullptr, nullptr, nullptr);
    node_reduce<<<BL, 128>>>(hV, ln1s, ln1b);
    ffn_mma<<<BL/32, 256, FF_SMEM>>>(maskV, bi, bo, ln2s, ln2b, outV);
    precomp_kernel<<<BL/64, 256, PC_SMEM>>>(outV, w11h, w11l);
    mma_stage<true><<<NTILE, 256, MS_SMEM>>>(hE, Eidx, maskA,
                                             b11, b12, b13, ln3s, ln3b, outE);
}

// round 16
// speedup vs baseline: 8.3695x; 1.2942x over previous
#include <cuda_runtime.h>
#include <cuda_fp16.h>
#include <math.h>
#include <stdint.h>

#define NB 2
#define NL 2048
#define NK 48
#define NH 128
#define BL (NB*NL)              // 4096
#define NEDGE (BL*NK)           // 196608
#define NTILE (NEDGE/128)       // 1536
#define SCALE_INV (1.0f/30.0f)
#define LNEPS 1e-5f

// fp16 smem row stride: 136 elems = 272B -> conflict-free ldmatrix
#define LDS_STRIDE 136
#define B_BYTES 34816                 // single-plane 128x136 fp16

// ---- mma_stage smem: A[128x136] + B[128x136] ----
#define MS_A 0
#define MS_B 34816
#define MS_SMEM (69632 + 1024)
#define STG_STRIDE 132                // fp32 stage aliases A+B region (67584 <= 69632)

// ---- precomp smem: A[64x136] + B ----
#define PC_A 0
#define PC_B 17408
#define PC_SMEM (52224 + 1024)

// ---- ffn smem ----
#define FF_A1 0                       // 32x136 fp16 = 8704
#define FF_A2 8704                    // 32x520 fp16 = 33280
#define FF_B0 41984
#define FF_B1 76800
#define FF_STG 111616                 // 32x132 fp32 = 16896
#define FF_SMEM (128512 + 1024)
#define A2_STRIDE 520

// ---- transposed fp16 weights (K-major [N][Ktot]) ----
__device__ __align__(16) __half g_W1h[128*384];
__device__ __align__(16) __half g_W2h[128*128];
__device__ __align__(16) __half g_W3h[128*128];
__device__ __align__(16) __half g_W11h[128*384];
__device__ __align__(16) __half g_W12h[128*128];
__device__ __align__(16) __half g_W13h[128*128];
__device__ __align__(16) __half g_Wih[512*128];    // Wi: K=128,N=512
__device__ __align__(16) __half g_Woh[128*512];    // Wo: K=512,N=128
__device__ float g_psum[2L*BL*NH];
__device__ float g_hV1[(long)BL*NH];
__device__ float g_Pa[(long)BL*NH];
__device__ float g_Pc[(long)BL*NH];

// ============================ helpers ============================
__device__ __forceinline__ uint32_t smem_u32(const void* p) {
    uint32_t a;
    asm("{ .reg .u64 t; cvta.to.shared.u64 t, %1; cvt.u32.u64 %0, t; }" : "=r"(a) : "l"(p));
    return a;
}
__device__ __forceinline__ void ldsm_x4(uint32_t* r, uint32_t addr) {
    asm volatile("ldmatrix.sync.aligned.m8n8.x4.shared.b16 {%0,%1,%2,%3}, [%4];"
        : "=r"(r[0]), "=r"(r[1]), "=r"(r[2]), "=r"(r[3]) : "r"(addr));
}
__device__ __forceinline__ void mma16816(float* d, const uint32_t* a, const uint32_t* b) {
    asm volatile("mma.sync.aligned.m16n8k16.row.col.f32.f16.f16.f32 "
        "{%0,%1,%2,%3}, {%4,%5,%6,%7}, {%8,%9}, {%0,%1,%2,%3};"
        : "+f"(d[0]), "+f"(d[1]), "+f"(d[2]), "+f"(d[3])
        : "r"(a[0]), "r"(a[1]), "r"(a[2]), "r"(a[3]), "r"(b[0]), "r"(b[1]));
}
#define CP_ASYNC16(dst, src) \
    asm volatile("cp.async.cg.shared.global [%0], [%1], 16;" :: "r"(dst), "l"(src))
#define CP_COMMIT() asm volatile("cp.async.commit_group;" ::: "memory")
#define CP_WAIT0()  asm volatile("cp.async.wait_group 0;" ::: "memory")

__device__ __forceinline__ float gelu_f(float x) {
    return 0.5f * x * (1.0f + erff(x * 0.70710678118654752f));
}
__device__ __forceinline__ float warp_sum(float v) {
    #pragma unroll
    for (int o = 16; o > 0; o >>= 1) v += __shfl_xor_sync(0xffffffffu, v, o);
    return v;
}
__device__ __forceinline__ uint32_t pack_h2(float x, float y) {
    __half2 h = __floats2half2_rn(x, y);
    return *(uint32_t*)&h;
}

// ============================ prep: transpose weights ============================
template<int K, int N>
__device__ __forceinline__ void conv_tr(const float* __restrict__ W, __half* H,
                                        int g, int gs) {
    for (int i = g; i < K * N; i += gs) {
        int n = i / K, k = i - n * K;
        H[(long)n * K + k] = __float2half_rn(W[(long)k * N + n]);
    }
}
__global__ void prep_weights(const float* W1, const float* W2, const float* W3,
                             const float* W11, const float* W12, const float* W13,
                             const float* Wi, const float* Wo) {
    int g = blockIdx.x * blockDim.x + threadIdx.x;
    int gs = gridDim.x * blockDim.x;
    conv_tr<384,128>(W1,  g_W1h,  g, gs);
    conv_tr<128,128>(W2,  g_W2h,  g, gs);
    conv_tr<128,128>(W3,  g_W3h,  g, gs);
    conv_tr<384,128>(W11, g_W11h, g, gs);
    conv_tr<128,128>(W12, g_W12h, g, gs);
    conv_tr<128,128>(W13, g_W13h, g, gs);
    conv_tr<128,512>(Wi,  g_Wih,  g, gs);
    conv_tr<512,128>(Wo,  g_Woh,  g, gs);
}

// ============================ building blocks ============================
// async B load: 128 rows x 128 fp16 (single plane)
__device__ __forceinline__ void asyncB(const __half* __restrict__ Wh,
                                       int Ktot, int kk, uint32_t bufAddr, int tid) {
    #pragma unroll
    for (int u = tid; u < 2048; u += 256) {
        int n = u >> 4, s = u & 15;
        uint32_t dst = bufAddr + n * (LDS_STRIDE * 2) + s * 16;
        CP_ASYNC16(dst, (const char*)(Wh + (long)n * Ktot + kk) + s * 16);
    }
    CP_COMMIT();
}

// build A fp16 from R contiguous fp32 rows (stride NH)
template<int R>
__device__ __forceinline__ void buildA_rows(const float* __restrict__ srcbase,
                                            __half* Ah, int tid) {
    #pragma unroll
    for (int u = tid; u < R * 32; u += 256) {
        int r = u >> 5, q = u & 31;
        float4 v = ((const float4*)(srcbase + (long)r * NH))[q];
        *(uint2*)(Ah + r * LDS_STRIDE + q * 4) =
            make_uint2(pack_h2(v.x, v.y), pack_h2(v.z, v.w));
    }
}

// generic 128-K chunk: warp tile (MT*16) rows x (NT*8) cols, single-plane fp16
template<int MT, int NT>
__device__ __forceinline__ void gemm_g(uint32_t aBase, int aStride, uint32_t bbase,
                                       int lane, int nbase, float acc[MT][NT][4]) {
    const int bRow0 = nbase + ((lane >> 4) & 1) * 8 + (lane & 7);
    const int bCol  = ((lane >> 3) & 1) * 8;
    #pragma unroll
    for (int ks = 0; ks < 8; ks++) {
        const uint32_t k0b = ks * 32;
        uint32_t ah[MT][4];
        #pragma unroll
        for (int mt = 0; mt < MT; mt++)
            ldsm_x4(ah[mt], aBase + mt * 16 * aStride + k0b);
        uint32_t bh[NT/2][4];
        #pragma unroll
        for (int p = 0; p < NT/2; p++) {
            uint32_t ba = (uint32_t)(((bRow0 + p * 16) * LDS_STRIDE + bCol) * 2) + k0b;
            ldsm_x4(bh[p], bbase + ba);
        }
        #pragma unroll
        for (int mt = 0; mt < MT; mt++)
            #pragma unroll
            for (int nt = 0; nt < NT; nt++)
                mma16816(acc[mt][nt], ah[mt], &bh[nt >> 1][(nt & 1) * 2]);
    }
}
template<int MT, int NT>
__device__ __forceinline__ void zero_g(float acc[MT][NT][4]) {
    #pragma unroll
    for (int mt = 0; mt < MT; mt++)
        #pragma unroll
        for (int nt = 0; nt < NT; nt++)
            #pragma unroll
            for (int j = 0; j < 4; j++) acc[mt][nt][j] = 0.f;
}

// ============================ precomp: Pa = src@W1a, Pc = src@W1c ============================
// 64 rows/CTA, 8 warps, warp tile 16x64 (MT=1, NT=8)
__global__ __launch_bounds__(256, 2)
void precomp_kernel(const float* __restrict__ src,
                    const __half* __restrict__ Wh) {
    extern __shared__ char dsm[];
    char* smA = (char*)(((uintptr_t)dsm + 1023) & ~(uintptr_t)1023);
    const int tid = threadIdx.x, wid = tid >> 5, lane = tid & 31;
    const long base = (long)blockIdx.x * 64;
    const int mbase = (wid & 3) * 16;
    const int nbase = (wid >> 2) * 64;
    const uint32_t sb = smem_u32(smA);
    const uint32_t aBase = sb + PC_A + (uint32_t)(((mbase + (lane & 15)) * LDS_STRIDE + ((lane >> 4) << 3)) * 2);
    const int g = lane >> 2, tig = lane & 3;

    asyncB(Wh, 384, 0, sb + PC_B, tid);               // W1a
    buildA_rows<64>(src + base * NH, (__half*)(smA + PC_A), tid);
    CP_WAIT0();
    __syncthreads();

    float acc[1][8][4];
    zero_g<1,8>(acc);
    gemm_g<1,8>(aBase, LDS_STRIDE*2, sb + PC_B, lane, nbase, acc);
    __syncthreads();                                  // all reads of B done
    asyncB(Wh, 384, 256, sb + PC_B, tid);             // W1c (overlaps writeP)
    #pragma unroll
    for (int nt = 0; nt < 8; nt++) {
        int col = nbase + nt * 8 + tig * 2;
        *(float2*)(g_Pa + (base + mbase + g) * NH + col)     = make_float2(acc[0][nt][0], acc[0][nt][1]);
        *(float2*)(g_Pa + (base + mbase + g + 8) * NH + col) = make_float2(acc[0][nt][2], acc[0][nt][3]);
    }
    CP_WAIT0();
    __syncthreads();
    zero_g<1,8>(acc);
    gemm_g<1,8>(aBase, LDS_STRIDE*2, sb + PC_B, lane, nbase, acc);
    #pragma unroll
    for (int nt = 0; nt < 8; nt++) {
        int col = nbase + nt * 8 + tig * 2;
        *(float2*)(g_Pc + (base + mbase + g) * NH + col)     = make_float2(acc[0][nt][0], acc[0][nt][1]);
        *(float2*)(g_Pc + (base + mbase + g + 8) * NH + col) = make_float2(acc[0][nt][2], acc[0][nt][3]);
    }
}

// ============================ MMA stage: 128 rows, 8 warps, warp tile 32x64 ============================
template<bool EDGE>
__global__ __launch_bounds__(256, 2)
void mma_stage(const float* __restrict__ hE,
               const int* __restrict__ Eidx,
               const float* __restrict__ maskA,
               const float* __restrict__ B1v, const float* __restrict__ B2v,
               const float* __restrict__ B3v,
               const float* __restrict__ lns, const float* __restrict__ lnb,
               float* __restrict__ outp) {
    extern __shared__ char dsm[];
    char* smA = (char*)(((uintptr_t)dsm + 1023) & ~(uintptr_t)1023);
    __half* Ah = (__half*)(smA + MS_A);
    float* stage = (float*)smA;                       // aliases A+B after final sync

    __shared__ int   gcent[128];
    __shared__ int   gnb[128];
    __shared__ float mkr[128];

    const int tid = threadIdx.x, wid = tid >> 5, lane = tid & 31;
    const long base = (long)blockIdx.x * 128;
    const int mbase = (wid & 3) * 32;
    const int nbase = (wid >> 2) * 64;
    const uint32_t sb = smem_u32(smA);
    const uint32_t aBase = sb + MS_A + (uint32_t)(((mbase + (lane & 15)) * LDS_STRIDE + ((lane >> 4) << 3)) * 2);
    const uint32_t bb = sb + MS_B;
    const int g = lane >> 2, tig = lane & 3;

    const __half* W1h = EDGE ? g_W11h : g_W1h;
    const __half* W2h = EDGE ? g_W12h : g_W2h;
    const __half* W3h = EDGE ? g_W13h : g_W3h;

    asyncB(W1h, 384, 128, bb, tid);                   // W1b (edge chunk)
    buildA_rows<128>(hE + base * NH, Ah, tid);

    if (tid < 128) {
        long e = base + tid;
        int n = (int)(e / NK);
        gcent[tid] = n;
        gnb[tid] = (n >> 11) * NL + Eidx[e];
        if (!EDGE) mkr[tid] = maskA[e]; else mkr[tid] = 1.f;
    }
    CP_WAIT0();
    __syncthreads();

    float acc[2][8][4];
    zero_g<2,8>(acc);
    gemm_g<2,8>(aBase, LDS_STRIDE*2, bb, lane, nbase, acc);
    __syncthreads();                                  // B reads complete
    asyncB(W2h, 128, 0, bb, tid);                     // overlaps epilogue 1

    // ---------- epilogue L1: D + Pa[cent] + Pc[nbr] + b1 -> gelu -> A ----------
    #pragma unroll
    for (int mt = 0; mt < 2; mt++) {
        int r0 = mbase + mt * 16 + g, r1 = r0 + 8;
        const float* pa0 = g_Pa + (long)gcent[r0] * NH;
        const float* pc0 = g_Pc + (long)gnb[r0] * NH;
        const float* pa1 = g_Pa + (long)gcent[r1] * NH;
        const float* pc1 = g_Pc + (long)gnb[r1] * NH;
        #pragma unroll
        for (int nt = 0; nt < 8; nt++) {
            int col = nbase + nt * 8 + tig * 2;
            float2 b2 = *(const float2*)(B1v + col);
            float2 a0 = *(const float2*)(pa0 + col);
            float2 c0 = *(const float2*)(pc0 + col);
            float2 a1 = *(const float2*)(pa1 + col);
            float2 c1 = *(const float2*)(pc1 + col);
            float x0 = gelu_f(acc[mt][nt][0] + b2.x + a0.x + c0.x);
            float x1 = gelu_f(acc[mt][nt][1] + b2.y + a0.y + c0.y);
            float x2 = gelu_f(acc[mt][nt][2] + b2.x + a1.x + c1.x);
            float x3 = gelu_f(acc[mt][nt][3] + b2.y + a1.y + c1.y);
            *(uint32_t*)(Ah + r0 * LDS_STRIDE + col) = pack_h2(x0, x1);
            *(uint32_t*)(Ah + r1 * LDS_STRIDE + col) = pack_h2(x2, x3);
        }
    }
    CP_WAIT0();
    __syncthreads();

    // ---------- GEMM2 ----------
    zero_g<2,8>(acc);
    gemm_g<2,8>(aBase, LDS_STRIDE*2, bb, lane, nbase, acc);
    __syncthreads();
    asyncB(W3h, 128, 0, bb, tid);                     // overlaps epilogue 2

    // ---------- epilogue L2: gelu(D+b2) -> A ----------
    #pragma unroll
    for (int mt = 0; mt < 2; mt++) {
        int r0 = mbase + mt * 16 + g, r1 = r0 + 8;
        #pragma unroll
        for (int nt = 0; nt < 8; nt++) {
            int col = nbase + nt * 8 + tig * 2;
            float2 b2 = *(const float2*)(B2v + col);
            float x0 = gelu_f(acc[mt][nt][0] + b2.x);
            float x1 = gelu_f(acc[mt][nt][1] + b2.y);
            float x2 = gelu_f(acc[mt][nt][2] + b2.x);
            float x3 = gelu_f(acc[mt][nt][3] + b2.y);
            *(uint32_t*)(Ah + r0 * LDS_STRIDE + col) = pack_h2(x0, x1);
            *(uint32_t*)(Ah + r1 * LDS_STRIDE + col) = pack_h2(x2, x3);
        }
    }
    CP_WAIT0();
    __syncthreads();

    // ---------- GEMM3 ----------
    zero_g<2,8>(acc);
    gemm_g<2,8>(aBase, LDS_STRIDE*2, bb, lane, nbase, acc);
    __syncthreads();                                  // A+B reads done -> stage may alias

    // ---------- final epilogue: bias (+mask) -> fp32 stage ----------
    #pragma unroll
    for (int mt = 0; mt < 2; mt++) {
        int r0 = mbase + mt * 16 + g;
        #pragma unroll
        for (int nt = 0; nt < 8; nt++) {
            int col = nbase + nt * 8 + tig * 2;
            float2 b2 = *(const float2*)(B3v + col);
            float2 z0, z1;
            z0.x = (acc[mt][nt][0] + b2.x) * mkr[r0];
            z0.y = (acc[mt][nt][1] + b2.y) * mkr[r0];
            z1.x = (acc[mt][nt][2] + b2.x) * mkr[r0 + 8];
            z1.y = (acc[mt][nt][3] + b2.y) * mkr[r0 + 8];
            *(float2*)(stage + r0 * STG_STRIDE + col) = z0;
            *(float2*)(stage + (r0 + 8) * STG_STRIDE + col) = z1;
        }
    }
    __syncthreads();

    if (!EDGE) {
        int c = tid & 127, half = tid >> 7;
        int n0 = (int)(base / NK), n1 = (int)((base + 127) / NK);
        for (int n = n0 + half; n <= n1; n += 2) {
            int r0 = n * NK - (int)base; if (r0 < 0) r0 = 0;
            int r1 = n * NK + NK - (int)base; if (r1 > 128) r1 = 128;
            float sacc = 0.f;
            for (int r = r0; r < r1; r++) sacc += stage[r * STG_STRIDE + c];
            int slot = (((n * NK) >> 7) == (int)blockIdx.x) ? 0 : 1;
            g_psum[(long)slot * BL * NH + (long)n * NH + c] = sacc;
        }
    } else {
        float4 sV = ((const float4*)lns)[lane];
        float4 bV = ((const float4*)lnb)[lane];
        #pragma unroll
        for (int i = 0; i < 16; i++) {
            int r = wid * 16 + i;
            long ge = base + r;
            float4 m = ((const float4*)(stage + r * STG_STRIDE))[lane];
            float4 e4 = ((const float4*)(hE + ge * NH))[lane];
            float4 v;
            v.x = e4.x + m.x; v.y = e4.y + m.y; v.z = e4.z + m.z; v.w = e4.w + m.w;
            float mu = warp_sum(v.x + v.y + v.z + v.w) * (1.0f / NH);
            float dx = v.x - mu, dy = v.y - mu, dz = v.z - mu, dw = v.w - mu;
            float var = warp_sum(dx * dx + dy * dy + dz * dz + dw * dw) * (1.0f / NH);
            float inv = rsqrtf(var + LNEPS);
            float4 o;
            o.x = dx * inv * sV.x + bV.x; o.y = dy * inv * sV.y + bV.y;
            o.z = dz * inv * sV.z + bV.z; o.w = dw * inv * sV.w + bV.w;
            ((float4*)(outp + ge * NH))[lane] = o;
        }
    }
}

// ============================ node reduce + LN1 ============================
__global__ void node_reduce(const float* __restrict__ hV, const float* __restrict__ lns,
                            const float* __restrict__ lnb) {
    __shared__ float red[8];
    int n = blockIdx.x, c = threadIdx.x;
    float p = g_psum[(long)n * NH + c];
    if (((n * NK) >> 7) != ((n * NK + NK - 1) >> 7))
        p += g_psum[(long)BL * NH + (long)n * NH + c];
    float h = hV[(long)n * NH + c] + p * SCALE_INV;
    float s = warp_sum(h);
    if ((c & 31) == 0) red[c >> 5] = s;
    __syncthreads();
    float mu = (red[0] + red[1] + red[2] + red[3]) * (1.0f / NH);
    float d = h - mu;
    float q = warp_sum(d * d);
    if ((c & 31) == 0) red[4 + (c >> 5)] = q;
    __syncthreads();
    float var = (red[4] + red[5] + red[6] + red[7]) * (1.0f / NH);
    g_hV1[(long)n * NH + c] = d * rsqrtf(var + LNEPS) * lns[c] + lnb[c];
}

// ============================ FFN: fp16 MMA, 32 rows/CTA ============================
__global__ __launch_bounds__(256, 1)
void ffn_mma(const float* __restrict__ maskV,
             const float* __restrict__ bi, const float* __restrict__ bo,
             const float* __restrict__ lns, const float* __restrict__ lnb,
             float* __restrict__ out) {
    extern __shared__ char dsm[];
    char* smA = (char*)(((uintptr_t)dsm + 1023) & ~(uintptr_t)1023);
    __half* A1 = (__half*)(smA + FF_A1);
    __half* A2 = (__half*)(smA + FF_A2);
    float* stage = (float*)(smA + FF_STG);

    const int tid = threadIdx.x, wid = tid >> 5, lane = tid & 31;
    const long rbase = (long)blockIdx.x * 32;
    const int mbase = (wid & 1) * 16;
    const int nbase = (wid >> 1) * 32;
    const uint32_t sb = smem_u32(smA);
    const int g = lane >> 2, tig = lane & 3;
    const uint32_t aBase1 = sb + FF_A1 + (uint32_t)(((mbase + (lane & 15)) * LDS_STRIDE + ((lane >> 4) << 3)) * 2);

    asyncB(g_Wih, 128, 0, sb + FF_B0, tid);           // Wi chunk 0
    buildA_rows<32>(g_hV1 + rbase * NH, A1, tid);
    CP_WAIT0();
    __syncthreads();

    // ---------- layer 1: 4 N-chunks of 128 ----------
    float acc[1][4][4];
    #pragma unroll 1
    for (int j = 0; j < 4; j++) {
        uint32_t cur = (j & 1) ? (sb + FF_B1) : (sb + FF_B0);
        uint32_t nxt = (j & 1) ? (sb + FF_B0) : (sb + FF_B1);
        if (j < 3) asyncB(g_Wih + (long)(j + 1) * 128 * 128, 128, 0, nxt, tid);
        else       asyncB(g_Woh, 512, 0, nxt, tid);
        zero_g<1,4>(acc);
        gemm_g<1,4>(aBase1, LDS_STRIDE*2, cur, lane, nbase, acc);
        #pragma unroll
        for (int nt = 0; nt < 4; nt++) {
            int col = nbase + nt * 8 + tig * 2;
            float2 b2 = *(const float2*)(bi + j * 128 + col);
            float x0 = gelu_f(acc[0][nt][0] + b2.x);
            float x1 = gelu_f(acc[0][nt][1] + b2.y);
            float x2 = gelu_f(acc[0][nt][2] + b2.x);
            float x3 = gelu_f(acc[0][nt][3] + b2.y);
            *(uint32_t*)(A2 + (mbase + g) * A2_STRIDE + j * 128 + col)     = pack_h2(x0, x1);
            *(uint32_t*)(A2 + (mbase + g + 8) * A2_STRIDE + j * 128 + col) = pack_h2(x2, x3);
        }
        CP_WAIT0();
        __syncthreads();
    }

    // ---------- layer 2: 4 K-chunks accumulate ----------
    float acc2[1][4][4];
    zero_g<1,4>(acc2);
    #pragma unroll 1
    for (int c = 0; c < 4; c++) {
        int ch = 4 + c;
        uint32_t cur = (ch & 1) ? (sb + FF_B1) : (sb + FF_B0);
        uint32_t nxt = (ch & 1) ? (sb + FF_B0) : (sb + FF_B1);
        if (c < 3) asyncB(g_Woh, 512, (c + 1) * 128, nxt, tid);
        uint32_t aBase2 = sb + FF_A2 +
            (uint32_t)(((mbase + (lane & 15)) * A2_STRIDE + ((lane >> 4) << 3) + c * 128) * 2);
        gemm_g<1,4>(aBase2, A2_STRIDE*2, cur, lane, nbase, acc2);
        CP_WAIT0();
        __syncthreads();
    }

    // ---------- final: + bo + residual -> stage ----------
    #pragma unroll
    for (int nt = 0; nt < 4; nt++) {
        int col = nbase + nt * 8 + tig * 2;
        float2 b2 = *(const float2*)(bo + col);
        float2 r0 = *(const float2*)(g_hV1 + (rbase + mbase + g) * NH + col);
        float2 r1 = *(const float2*)(g_hV1 + (rbase + mbase + g + 8) * NH + col);
        float2 z0, z1;
        z0.x = acc2[0][nt][0] + b2.x + r0.x;
        z0.y = acc2[0][nt][1] + b2.y + r0.y;
        z1.x = acc2[0][nt][2] + b2.x + r1.x;
        z1.y = acc2[0][nt][3] + b2.y + r1.y;
        *(float2*)(stage + (mbase + g) * STG_STRIDE + col) = z0;
        *(float2*)(stage + (mbase + g + 8) * STG_STRIDE + col) = z1;
    }
    __syncthreads();

    // ---------- per-row LN2 + mask_V -> out ----------
    {
        float4 sV = ((const float4*)lns)[lane];
        float4 bV = ((const float4*)lnb)[lane];
        #pragma unroll
        for (int rr = 0; rr < 4; rr++) {
            int r = wid * 4 + rr;
            long grow = rbase + r;
            float mk = maskV[grow];
            float4 v = ((const float4*)(stage + r * STG_STRIDE))[lane];
            float mu = warp_sum(v.x + v.y + v.z + v.w) * (1.0f / NH);
            float dx = v.x - mu, dy = v.y - mu, dz = v.z - mu, dw = v.w - mu;
            float var = warp_sum(dx * dx + dy * dy + dz * dz + dw * dw) * (1.0f / NH);
            float inv = rsqrtf(var + LNEPS);
            float4 o;
            o.x = (dx * inv * sV.x + bV.x) * mk; o.y = (dy * inv * sV.y + bV.y) * mk;
            o.z = (dz * inv * sV.z + bV.z) * mk; o.w = (dw * inv * sV.w + bV.w) * mk;
            ((float4*)(out + grow * NH))[lane] = o;
        }
    }
}

// ============================ host ============================
extern "C" void kernel_launch(void* const* d_in, const int* in_sizes, int n_in,
                              void* d_out, int out_size) {
    (void)in_sizes; (void)n_in; (void)out_size;
    const float* hV    = (const float*)d_in[0];
    const float* hE    = (const float*)d_in[1];
    const int*   Eidx  = (const int*)d_in[2];
    const float* maskV = (const float*)d_in[3];
    const float* maskA = (const float*)d_in[4];
    const float *W1 =(const float*)d_in[5],  *b1 =(const float*)d_in[6];
    const float *W2 =(const float*)d_in[7],  *b2 =(const float*)d_in[8];
    const float *W3 =(const float*)d_in[9],  *b3 =(const float*)d_in[10];
    const float *W11=(const float*)d_in[11], *b11=(const float*)d_in[12];
    const float *W12=(const float*)d_in[13], *b12=(const float*)d_in[14];
    const float *W13=(const float*)d_in[15], *b13=(const float*)d_in[16];
    const float *Wi =(const float*)d_in[17], *bi =(const float*)d_in[18];
    const float *Wo =(const float*)d_in[19], *bo =(const float*)d_in[20];
    const float *ln1s=(const float*)d_in[21], *ln1b=(const float*)d_in[22];
    const float *ln2s=(const float*)d_in[23], *ln2b=(const float*)d_in[24];
    const float *ln3s=(const float*)d_in[25], *ln3b=(const float*)d_in[26];

    float* outV = (float*)d_out;
    float* outE = outV + (long)BL*NH;

    cudaFuncSetAttribute(mma_stage<false>, cudaFuncAttributeMaxDynamicSharedMemorySize, MS_SMEM);
    cudaFuncSetAttribute(mma_stage<true>,  cudaFuncAttributeMaxDynamicSharedMemorySize, MS_SMEM);
    cudaFuncSetAttribute(precomp_kernel,   cudaFuncAttributeMaxDynamicSharedMemorySize, PC_SMEM);
    cudaFuncSetAttribute(ffn_mma,          cudaFuncAttributeMaxDynamicSharedMemorySize, FF_SMEM);

    __half *w1h, *w11h;
    cudaGetSymbolAddress((void**)&w1h,  g_W1h);
    cudaGetSymbolAddress((void**)&w11h, g_W11h);

    prep_weights<<<148, 256>>>(W1, W2, W3, W11, W12, W13, Wi, Wo);
    precomp_kernel<<<BL/64, 256, PC_SMEM>>>(hV, w1h);
    mma_stage<false><<<NTILE, 256, MS_SMEM>>>(hE, Eidx, maskA,
                                              b1, b2, b3, nullptr, nullptr, nullptr);
    node_reduce<<<BL, 128>>>(hV, ln1s, ln1b);
    ffn_mma<<<BL/32, 256, FF_SMEM>>>(maskV, bi, bo, ln2s, ln2b, outV);
    precomp_kernel<<<BL/64, 256, PC_SMEM>>>(outV, w11h);
    mma_stage<true><<<NTILE, 256, MS_SMEM>>>(hE, Eidx, maskA,
                                             b11, b12, b13, ln3s, ln3b, outE);
}